// round 1
// baseline (speedup 1.0000x reference)
#include <cuda_runtime.h>
#include <math.h>

#define NB 2
#define NL 2048
#define NLC 2048
#define NH 16
#define DHD 64
#define DMODEL 1024
#define NROWS (NB*NL)   // 4096 (same for cross: NB*NLC)

// ---------------- scratch (device globals; no runtime allocation) ----------------
__device__ float g_xn[NROWS*DMODEL];     // rmsnorm(x)
__device__ float g_xc[NROWS*DMODEL];     // rmsnorm(x_cross)
__device__ float g_q [NROWS*DMODEL];     // q projection (then prepped in-place)
__device__ float g_kv[NROWS*2*DMODEL];   // kv projection (k prepped in-place)
__device__ float g_o [NROWS*DMODEL];     // attention output [b,l,h,d]

// ---------------- RMS norm ----------------
__global__ __launch_bounds__(256) void rmsnorm_k(const float* __restrict__ x,
                                                 const float* __restrict__ scale,
                                                 float* __restrict__ out) {
    int row = blockIdx.x;
    const float* xr = x + (size_t)row * DMODEL;
    float ss = 0.f;
    #pragma unroll
    for (int i = threadIdx.x; i < DMODEL; i += 256) { float v = xr[i]; ss += v*v; }
    __shared__ float red[256];
    red[threadIdx.x] = ss;
    __syncthreads();
    #pragma unroll
    for (int s = 128; s > 0; s >>= 1) {
        if (threadIdx.x < s) red[threadIdx.x] += red[threadIdx.x + s];
        __syncthreads();
    }
    float inv = rsqrtf(red[0] * (1.0f/DMODEL) + 1e-6f);
    #pragma unroll
    for (int i = threadIdx.x; i < DMODEL; i += 256)
        out[(size_t)row*DMODEL + i] = xr[i] * scale[i] * inv;
}

// ---------------- GEMM: C[M,N] = A[M,K] @ B[N,K]^T (+ skip) ----------------
// 128x128 block tile, 16 k-tile, 256 threads, 8x8 micro-tile per thread.
template<bool ADD>
__global__ __launch_bounds__(256) void gemm_abt(const float* __restrict__ A,
                                                const float* __restrict__ Bm,
                                                const float* __restrict__ skip,
                                                float* __restrict__ C,
                                                int M, int N, int K) {
    __shared__ __align__(16) float As[16*132];
    __shared__ __align__(16) float Bs[16*132];
    const int bm = blockIdx.y * 128, bn = blockIdx.x * 128;
    const int tid = threadIdx.x, ty = tid >> 4, tx = tid & 15;
    float acc[8][8] = {};
    for (int k0 = 0; k0 < K; k0 += 16) {
        #pragma unroll
        for (int r = 0; r < 8; r++) {
            int i = tid + r*256;
            int m = i >> 4, k = i & 15;
            As[k*132 + m] = A[(size_t)(bm + m)*K + k0 + k];
            Bs[k*132 + m] = Bm[(size_t)(bn + m)*K + k0 + k];
        }
        __syncthreads();
        #pragma unroll
        for (int kt = 0; kt < 16; kt++) {
            float4 a0 = *(const float4*)&As[kt*132 + ty*8];
            float4 a1 = *(const float4*)&As[kt*132 + ty*8 + 4];
            float4 b0 = *(const float4*)&Bs[kt*132 + tx*8];
            float4 b1 = *(const float4*)&Bs[kt*132 + tx*8 + 4];
            float av[8] = {a0.x,a0.y,a0.z,a0.w,a1.x,a1.y,a1.z,a1.w};
            float bv[8] = {b0.x,b0.y,b0.z,b0.w,b1.x,b1.y,b1.z,b1.w};
            #pragma unroll
            for (int i = 0; i < 8; i++)
                #pragma unroll
                for (int j = 0; j < 8; j++)
                    acc[i][j] = fmaf(av[i], bv[j], acc[i][j]);
        }
        __syncthreads();
    }
    #pragma unroll
    for (int i = 0; i < 8; i++) {
        size_t m = bm + ty*8 + i;
        #pragma unroll
        for (int j = 0; j < 8; j++) {
            size_t n = bn + tx*8 + j;
            float v = acc[i][j];
            if (ADD) v += skip[m*N + n];
            C[m*N + n] = v;
        }
    }
}

// ---------------- cosine scale + 3-axis RoPE (in-place on q or k) ----------------
// One 64-thread group per (row, head) vector. 4 groups per block.
__global__ __launch_bounds__(256) void qkprep_k(float* __restrict__ data,
                                                const float* __restrict__ pos,
                                                const float* __restrict__ head_scale,
                                                int stride) {
    const int g  = threadIdx.x >> 6;
    const int d  = threadIdx.x & 63;
    const int gv = blockIdx.x*4 + g;
    const int row = gv >> 4;
    const int h   = gv & 15;
    size_t idx = (size_t)row*stride + h*64 + d;
    float v = data[idx];

    __shared__ float sv[4][64];
    __shared__ float sred[4][64];
    sv[g][d] = v;
    sred[g][d] = v*v;
    __syncthreads();
    #pragma unroll
    for (int s = 32; s > 0; s >>= 1) {
        if (d < s) sred[g][d] += sred[g][d + s];
        __syncthreads();
    }
    float cs = sqrtf(head_scale[h]) * rsqrtf(sred[g][0] + 1e-6f);

    float out;
    if (d < 60) {
        int i = (d < 30) ? d : d - 30;
        int a = i / 10, j = i % 10;
        // freqs[h][j] = pi * 10^((j*16 + h)/160)
        float fr = 3.14159265358979323846f * exp10f((float)(j*16 + h) * (1.0f/160.0f));
        float th = pos[(size_t)row*3 + a] * fr;
        float sn, c;
        sincosf(th, &sn, &c);
        if (d < 30) out = cs * (v*c - sv[g][d + 30]*sn);
        else        out = cs * (v*c + sv[g][d - 30]*sn);
    } else {
        out = cs * v;
    }
    data[idx] = out;
}

// ---------------- flash attention (fp32, 64x64 tiles) ----------------
// sw4: XOR swizzle at float4 granularity within a 64-float row (bank-conflict free,
// no padding -> Qs + KP + Vs = exactly 48KB static smem).
__device__ __forceinline__ int sw4(int r, int c) {
    return (r << 6) + ((((c >> 2) ^ (r & 15)) << 2) | (c & 3));
}

__global__ __launch_bounds__(256) void attn_k(const float* __restrict__ Q,
                                              const float* __restrict__ KV,
                                              float* __restrict__ O) {
    __shared__ __align__(16) float Qs[64*64];   // [k][m] swizzled
    __shared__ __align__(16) float KP[64*64];   // K as [k][n] swizzled, reused as P [n][m]
    __shared__ __align__(16) float Vs[64*64];   // [n][d] natural
    const int b = blockIdx.z, h = blockIdx.y, m0 = blockIdx.x * 64;
    const int tid = threadIdx.x, ty = tid >> 4, tx = tid & 15;

    for (int i = tid; i < 4096; i += 256) {
        int m = i >> 6, d = i & 63;
        Qs[sw4(d, m)] = Q[((size_t)(b*NL + m0 + m)*NH + h)*64 + d];
    }

    float o_acc[4][4] = {};
    float row_max[4], row_sum[4];
    #pragma unroll
    for (int i = 0; i < 4; i++) { row_max[i] = -INFINITY; row_sum[i] = 0.f; }

    for (int n0 = 0; n0 < NLC; n0 += 64) {
        __syncthreads();  // prior PV reads of KP/Vs done (also covers initial Qs fill)
        for (int i = tid; i < 4096; i += 256) {
            int n = i >> 6, d = i & 63;
            size_t base = (size_t)(b*NLC + n0 + n)*(2*DMODEL) + h*64 + d;
            KP[sw4(d, n)]   = KV[base];
            Vs[(n << 6) + d] = KV[base + DMODEL];
        }
        __syncthreads();

        // S = Q K^T  (4x4 per thread)
        float s[4][4] = {};
        #pragma unroll 8
        for (int kk = 0; kk < 64; kk++) {
            float4 a  = *(const float4*)&Qs[sw4(kk, ty << 2)];
            float4 bb = *(const float4*)&KP[sw4(kk, tx << 2)];
            float av[4] = {a.x, a.y, a.z, a.w};
            float bv[4] = {bb.x, bb.y, bb.z, bb.w};
            #pragma unroll
            for (int i = 0; i < 4; i++)
                #pragma unroll
                for (int j = 0; j < 4; j++)
                    s[i][j] = fmaf(av[i], bv[j], s[i][j]);
        }

        // online softmax (row groups = 16 contiguous lanes; shfl stays in-group)
        #pragma unroll
        for (int i = 0; i < 4; i++) {
            float mx = fmaxf(fmaxf(s[i][0], s[i][1]), fmaxf(s[i][2], s[i][3]));
            #pragma unroll
            for (int off = 8; off; off >>= 1)
                mx = fmaxf(mx, __shfl_xor_sync(0xffffffffu, mx, off));
            float mnew = fmaxf(row_max[i], mx);
            float corr = __expf(row_max[i] - mnew);
            row_max[i] = mnew;
            float ls = 0.f;
            #pragma unroll
            for (int j = 0; j < 4; j++) { s[i][j] = __expf(s[i][j] - mnew); ls += s[i][j]; }
            #pragma unroll
            for (int off = 8; off; off >>= 1)
                ls += __shfl_xor_sync(0xffffffffu, ls, off);
            row_sum[i] = row_sum[i]*corr + ls;
            #pragma unroll
            for (int j = 0; j < 4; j++) o_acc[i][j] *= corr;
        }

        __syncthreads();  // everyone done reading K half of KP
        #pragma unroll
        for (int j = 0; j < 4; j++) {
            float4 t = make_float4(s[0][j], s[1][j], s[2][j], s[3][j]);
            *(float4*)&KP[sw4((tx << 2) + j, ty << 2)] = t;   // P stored [n][m]
        }
        __syncthreads();

        // O += P V
        #pragma unroll 8
        for (int nn = 0; nn < 64; nn++) {
            float4 p = *(const float4*)&KP[sw4(nn, ty << 2)];
            float4 v = *(const float4*)&Vs[(nn << 6) + (tx << 2)];
            float pv[4] = {p.x, p.y, p.z, p.w};
            float vv[4] = {v.x, v.y, v.z, v.w};
            #pragma unroll
            for (int i = 0; i < 4; i++)
                #pragma unroll
                for (int j = 0; j < 4; j++)
                    o_acc[i][j] = fmaf(pv[i], vv[j], o_acc[i][j]);
        }
    }

    #pragma unroll
    for (int i = 0; i < 4; i++) {
        float inv = 1.f / row_sum[i];
        #pragma unroll
        for (int j = 0; j < 4; j++) {
            O[((size_t)(b*NL + m0 + (ty << 2) + i)*NH + h)*64 + (tx << 2) + j]
                = o_acc[i][j] * inv;
        }
    }
}

// ---------------- launcher ----------------
extern "C" void kernel_launch(void* const* d_in, const int* in_sizes, int n_in,
                              void* d_out, int out_size) {
    const float* x      = (const float*)d_in[0];
    const float* pos    = (const float*)d_in[1];
    const float* x_cross= (const float*)d_in[2];
    const float* posc   = (const float*)d_in[3];
    const float* nscale = (const float*)d_in[4];
    const float* ncscale= (const float*)d_in[5];
    const float* q_w    = (const float*)d_in[6];
    const float* kv_w   = (const float*)d_in[7];
    const float* hscale = (const float*)d_in[8];
    const float* out_w  = (const float*)d_in[9];
    float* out = (float*)d_out;

    float *xn, *xc, *q, *kv, *o;
    cudaGetSymbolAddress((void**)&xn, g_xn);
    cudaGetSymbolAddress((void**)&xc, g_xc);
    cudaGetSymbolAddress((void**)&q,  g_q);
    cudaGetSymbolAddress((void**)&kv, g_kv);
    cudaGetSymbolAddress((void**)&o,  g_o);

    rmsnorm_k<<<NROWS, 256>>>(x, nscale, xn);
    rmsnorm_k<<<NROWS, 256>>>(x_cross, ncscale, xc);

    gemm_abt<false><<<dim3(DMODEL/128,   NROWS/128), 256>>>(xn, q_w,  nullptr, q,  NROWS, DMODEL,   DMODEL);
    gemm_abt<false><<<dim3(2*DMODEL/128, NROWS/128), 256>>>(xc, kv_w, nullptr, kv, NROWS, 2*DMODEL, DMODEL);

    qkprep_k<<<NROWS*NH/4, 256>>>(q,  pos,  hscale, DMODEL);
    qkprep_k<<<NROWS*NH/4, 256>>>(kv, posc, hscale, 2*DMODEL);

    attn_k<<<dim3(NL/64, NH, NB), 256>>>(q, kv, o);

    gemm_abt<true><<<dim3(DMODEL/128, NROWS/128), 256>>>(o, out_w, x, out, NROWS, DMODEL, DMODEL);
}

// round 2
// speedup vs baseline: 2.8314x; 2.8314x over previous
#include <cuda_runtime.h>
#include <math.h>

#define NB 2
#define NL 2048
#define NLC 2048
#define NH 16
#define DMODEL 1024
#define NROWS (NB*NL)

// ---------------- scratch ----------------
__device__ float g_xn[NROWS*DMODEL];
__device__ float g_xc[NROWS*DMODEL];
__device__ float g_q [NROWS*DMODEL];
__device__ float g_kv[NROWS*2*DMODEL];
__device__ float g_o [NROWS*DMODEL];

// ---------------- helpers ----------------
__device__ __forceinline__ unsigned f2tf(float f) {
    unsigned u; asm("cvt.rna.tf32.f32 %0, %1;" : "=r"(u) : "f"(f)); return u;
}
__device__ __forceinline__ void mma8(float* d, const unsigned* a, const unsigned* b) {
    asm("mma.sync.aligned.m16n8k8.row.col.f32.tf32.tf32.f32 "
        "{%0,%1,%2,%3},{%4,%5,%6,%7},{%8,%9},{%0,%1,%2,%3};"
        : "+f"(d[0]), "+f"(d[1]), "+f"(d[2]), "+f"(d[3])
        : "r"(a[0]), "r"(a[1]), "r"(a[2]), "r"(a[3]), "r"(b[0]), "r"(b[1]));
}

// swizzles: XOR at float4 granularity within a row
#define SWZ32(r,c) ((r)*32 + (((((c)>>2) ^ ((r)&7)) & 7)<<2) + ((c)&3))   // 32-wide rows
#define SWZ64(r,c) ((r)*64 + (((((c)>>2) ^ ((r)&15)) & 15)<<2) + ((c)&3)) // 64-wide rows

// ---------------- RMS norm ----------------
__global__ __launch_bounds__(256) void rmsnorm_k(const float* __restrict__ x,
                                                 const float* __restrict__ scale,
                                                 float* __restrict__ out) {
    int row = blockIdx.x;
    const float* xr = x + (size_t)row * DMODEL;
    float ss = 0.f;
    #pragma unroll
    for (int i = threadIdx.x; i < DMODEL; i += 256) { float v = xr[i]; ss += v*v; }
    __shared__ float red[256];
    red[threadIdx.x] = ss;
    __syncthreads();
    #pragma unroll
    for (int s = 128; s > 0; s >>= 1) {
        if (threadIdx.x < s) red[threadIdx.x] += red[threadIdx.x + s];
        __syncthreads();
    }
    float inv = rsqrtf(red[0] * (1.0f/DMODEL) + 1e-6f);
    #pragma unroll
    for (int i = threadIdx.x; i < DMODEL; i += 256)
        out[(size_t)row*DMODEL + i] = xr[i] * scale[i] * inv;
}

// ---------------- tf32 tensor-core GEMM: C[M,N] = A[M,K] @ B[N,K]^T (+skip) ----------------
// 128x128 block, 8 warps (2x4), warp tile 64x32, kt=32.
template<bool ADD>
__global__ __launch_bounds__(256) void gemm_tf32(const float* __restrict__ A,
                                                 const float* __restrict__ Bm,
                                                 const float* __restrict__ skip,
                                                 float* __restrict__ C,
                                                 int M, int N, int K) {
    __shared__ __align__(16) unsigned As[128*32];
    __shared__ __align__(16) unsigned Bs[128*32];
    const int bm = blockIdx.y * 128, bn = blockIdx.x * 128;
    const int tid = threadIdx.x, w = tid >> 5, lane = tid & 31;
    const int g = lane >> 2, t = lane & 3;
    const int wm = (w >> 2) * 64, wn = (w & 3) * 32;

    float acc[4][4][4] = {};

    for (int k0 = 0; k0 < K; k0 += 32) {
        #pragma unroll
        for (int r = 0; r < 4; r++) {
            int idx = tid + r*256;
            int row = idx >> 3, c4 = idx & 7;
            float4 va = *(const float4*)&A [(size_t)(bm + row)*K + k0 + c4*4];
            float4 vb = *(const float4*)&Bm[(size_t)(bn + row)*K + k0 + c4*4];
            int sc = row*32 + ((c4 ^ (row & 7)) << 2);
            *(uint4*)&As[sc] = make_uint4(f2tf(va.x), f2tf(va.y), f2tf(va.z), f2tf(va.w));
            *(uint4*)&Bs[sc] = make_uint4(f2tf(vb.x), f2tf(vb.y), f2tf(vb.z), f2tf(vb.w));
        }
        __syncthreads();
        #pragma unroll
        for (int ks = 0; ks < 4; ks++) {
            unsigned af[4][4], bf[4][2];
            int c0 = ks*8 + t;
            #pragma unroll
            for (int mt = 0; mt < 4; mt++) {
                int r0 = wm + mt*16 + g;
                af[mt][0] = As[SWZ32(r0,     c0)];
                af[mt][1] = As[SWZ32(r0 + 8, c0)];
                af[mt][2] = As[SWZ32(r0,     c0 + 4)];
                af[mt][3] = As[SWZ32(r0 + 8, c0 + 4)];
            }
            #pragma unroll
            for (int nt = 0; nt < 4; nt++) {
                int rn = wn + nt*8 + g;
                bf[nt][0] = Bs[SWZ32(rn, c0)];
                bf[nt][1] = Bs[SWZ32(rn, c0 + 4)];
            }
            #pragma unroll
            for (int mt = 0; mt < 4; mt++)
                #pragma unroll
                for (int nt = 0; nt < 4; nt++)
                    mma8(acc[mt][nt], af[mt], bf[nt]);
        }
        __syncthreads();
    }

    #pragma unroll
    for (int mt = 0; mt < 4; mt++) {
        size_t r0 = bm + wm + mt*16 + g, r1 = r0 + 8;
        #pragma unroll
        for (int nt = 0; nt < 4; nt++) {
            size_t cc = bn + wn + nt*8 + 2*t;
            float2 v0 = make_float2(acc[mt][nt][0], acc[mt][nt][1]);
            float2 v1 = make_float2(acc[mt][nt][2], acc[mt][nt][3]);
            if (ADD) {
                float2 s0 = *(const float2*)&skip[r0*N + cc];
                float2 s1 = *(const float2*)&skip[r1*N + cc];
                v0.x += s0.x; v0.y += s0.y; v1.x += s1.x; v1.y += s1.y;
            }
            *(float2*)&C[r0*N + cc] = v0;
            *(float2*)&C[r1*N + cc] = v1;
        }
    }
}

// ---------------- cosine scale + 3-axis RoPE (in-place) ----------------
__global__ __launch_bounds__(256) void qkprep_k(float* __restrict__ data,
                                                const float* __restrict__ pos,
                                                const float* __restrict__ head_scale,
                                                int stride) {
    const int g  = threadIdx.x >> 6;
    const int d  = threadIdx.x & 63;
    const int gv = blockIdx.x*4 + g;
    const int row = gv >> 4;
    const int h   = gv & 15;
    size_t idx = (size_t)row*stride + h*64 + d;
    float v = data[idx];

    __shared__ float sv[4][64];
    __shared__ float sred[4][64];
    sv[g][d] = v;
    sred[g][d] = v*v;
    __syncthreads();
    #pragma unroll
    for (int s = 32; s > 0; s >>= 1) {
        if (d < s) sred[g][d] += sred[g][d + s];
        __syncthreads();
    }
    float cs = sqrtf(head_scale[h]) * rsqrtf(sred[g][0] + 1e-6f);

    float out;
    if (d < 60) {
        int i = (d < 30) ? d : d - 30;
        int a = i / 10, j = i % 10;
        float fr = 3.14159265358979323846f * exp10f((float)(j*16 + h) * (1.0f/160.0f));
        float th = pos[(size_t)row*3 + a] * fr;
        float sn, c;
        sincosf(th, &sn, &c);
        if (d < 30) out = cs * (v*c - sv[g][d + 30]*sn);
        else        out = cs * (v*c + sv[g][d - 30]*sn);
    } else {
        out = cs * v;
    }
    data[idx] = out;
}

// ---------------- flash attention, tf32 tensor cores ----------------
// 64x64 tiles, 4 warps (each owns 16 q-rows). K buffer reused for P. 48KB static smem.
__global__ __launch_bounds__(128) void attn_tf32(const float* __restrict__ Q,
                                                 const float* __restrict__ KV,
                                                 float* __restrict__ O) {
    __shared__ __align__(16) unsigned Qs[64*64];
    __shared__ __align__(16) unsigned KP[64*64];   // K tile, then reused as P tile
    __shared__ __align__(16) unsigned Vs[64*64];
    const int b = blockIdx.z, h = blockIdx.y, m0 = blockIdx.x * 64;
    const int tid = threadIdx.x, w = tid >> 5, lane = tid & 31;
    const int g = lane >> 2, t = lane & 3;

    // load Q tile (fp32 -> tf32, swizzled [m][d])
    #pragma unroll
    for (int r = 0; r < 8; r++) {
        int idx = tid + r*128;
        int row = idx >> 4, c4 = idx & 15;
        float4 v = *(const float4*)&Q[((size_t)(b*NL + m0 + row)*NH + h)*64 + c4*4];
        *(uint4*)&Qs[row*64 + ((c4 ^ (row & 15)) << 2)] =
            make_uint4(f2tf(v.x), f2tf(v.y), f2tf(v.z), f2tf(v.w));
    }

    float o_acc[8][4] = {};
    float rm0 = -INFINITY, rm1 = -INFINITY, rs0 = 0.f, rs1 = 0.f;

    for (int n0 = 0; n0 < NLC; n0 += 64) {
        __syncthreads();   // prior iter done reading KP/Vs (also guards Qs fill)
        #pragma unroll
        for (int r = 0; r < 8; r++) {
            int idx = tid + r*128;
            int row = idx >> 4, c4 = idx & 15;
            size_t base = (size_t)(b*NLC + n0 + row)*(2*DMODEL) + h*64 + c4*4;
            float4 kvec = *(const float4*)&KV[base];
            float4 vvec = *(const float4*)&KV[base + DMODEL];
            int sc = row*64 + ((c4 ^ (row & 15)) << 2);
            *(uint4*)&KP[sc] = make_uint4(f2tf(kvec.x), f2tf(kvec.y), f2tf(kvec.z), f2tf(kvec.w));
            *(uint4*)&Vs[sc] = make_uint4(f2tf(vvec.x), f2tf(vvec.y), f2tf(vvec.z), f2tf(vvec.w));
        }
        __syncthreads();

        // S = Q K^T : warp computes 16 rows x 64 keys
        float s[8][4] = {};
        #pragma unroll
        for (int ks = 0; ks < 8; ks++) {
            int c0 = ks*8 + t;
            int r0 = 16*w + g;
            unsigned aq[4];
            aq[0] = Qs[SWZ64(r0,     c0)];
            aq[1] = Qs[SWZ64(r0 + 8, c0)];
            aq[2] = Qs[SWZ64(r0,     c0 + 4)];
            aq[3] = Qs[SWZ64(r0 + 8, c0 + 4)];
            #pragma unroll
            for (int nt = 0; nt < 8; nt++) {
                unsigned bk[2];
                bk[0] = KP[SWZ64(nt*8 + g, c0)];
                bk[1] = KP[SWZ64(nt*8 + g, c0 + 4)];
                mma8(s[nt], aq, bk);
            }
        }

        // online softmax: rows r0 = 16w+g, r1 = r0+8
        float mx0 = -INFINITY, mx1 = -INFINITY;
        #pragma unroll
        for (int nt = 0; nt < 8; nt++) {
            mx0 = fmaxf(mx0, fmaxf(s[nt][0], s[nt][1]));
            mx1 = fmaxf(mx1, fmaxf(s[nt][2], s[nt][3]));
        }
        #pragma unroll
        for (int off = 1; off <= 2; off <<= 1) {
            mx0 = fmaxf(mx0, __shfl_xor_sync(0xffffffffu, mx0, off));
            mx1 = fmaxf(mx1, __shfl_xor_sync(0xffffffffu, mx1, off));
        }
        float mn0 = fmaxf(rm0, mx0), mn1 = fmaxf(rm1, mx1);
        float cr0 = __expf(rm0 - mn0), cr1 = __expf(rm1 - mn1);
        rm0 = mn0; rm1 = mn1;
        float ls0 = 0.f, ls1 = 0.f;
        #pragma unroll
        for (int nt = 0; nt < 8; nt++) {
            s[nt][0] = __expf(s[nt][0] - mn0);
            s[nt][1] = __expf(s[nt][1] - mn0);
            s[nt][2] = __expf(s[nt][2] - mn1);
            s[nt][3] = __expf(s[nt][3] - mn1);
            ls0 += s[nt][0] + s[nt][1];
            ls1 += s[nt][2] + s[nt][3];
        }
        #pragma unroll
        for (int off = 1; off <= 2; off <<= 1) {
            ls0 += __shfl_xor_sync(0xffffffffu, ls0, off);
            ls1 += __shfl_xor_sync(0xffffffffu, ls1, off);
        }
        rs0 = rs0*cr0 + ls0;
        rs1 = rs1*cr1 + ls1;
        #pragma unroll
        for (int nt = 0; nt < 8; nt++) {
            o_acc[nt][0] *= cr0; o_acc[nt][1] *= cr0;
            o_acc[nt][2] *= cr1; o_acc[nt][3] *= cr1;
        }

        __syncthreads();   // all warps done reading K from KP
        // write P[m][key] (tf32) into KP
        #pragma unroll
        for (int nt = 0; nt < 8; nt++) {
            int kc = nt*8 + 2*t;
            int r0 = 16*w + g;
            KP[SWZ64(r0,     kc)]     = f2tf(s[nt][0]);
            KP[SWZ64(r0,     kc + 1)] = f2tf(s[nt][1]);
            KP[SWZ64(r0 + 8, kc)]     = f2tf(s[nt][2]);
            KP[SWZ64(r0 + 8, kc + 1)] = f2tf(s[nt][3]);
        }
        __syncthreads();

        // O += P V
        #pragma unroll
        for (int ks = 0; ks < 8; ks++) {
            int c0 = ks*8 + t;
            int r0 = 16*w + g;
            unsigned ap[4];
            ap[0] = KP[SWZ64(r0,     c0)];
            ap[1] = KP[SWZ64(r0 + 8, c0)];
            ap[2] = KP[SWZ64(r0,     c0 + 4)];
            ap[3] = KP[SWZ64(r0 + 8, c0 + 4)];
            #pragma unroll
            for (int nt = 0; nt < 8; nt++) {
                unsigned bv[2];
                bv[0] = Vs[SWZ64(c0,     nt*8 + g)];
                bv[1] = Vs[SWZ64(c0 + 4, nt*8 + g)];
                mma8(o_acc[nt], ap, bv);
            }
        }
    }

    float inv0 = 1.f / rs0, inv1 = 1.f / rs1;
    size_t r0 = m0 + 16*w + g, r1 = r0 + 8;
    #pragma unroll
    for (int nt = 0; nt < 8; nt++) {
        size_t cc = nt*8 + 2*t;
        *(float2*)&O[((size_t)(b*NL + r0)*NH + h)*64 + cc] =
            make_float2(o_acc[nt][0]*inv0, o_acc[nt][1]*inv0);
        *(float2*)&O[((size_t)(b*NL + r1)*NH + h)*64 + cc] =
            make_float2(o_acc[nt][2]*inv1, o_acc[nt][3]*inv1);
    }
}

// ---------------- launcher ----------------
extern "C" void kernel_launch(void* const* d_in, const int* in_sizes, int n_in,
                              void* d_out, int out_size) {
    const float* x      = (const float*)d_in[0];
    const float* pos    = (const float*)d_in[1];
    const float* x_cross= (const float*)d_in[2];
    const float* posc   = (const float*)d_in[3];
    const float* nscale = (const float*)d_in[4];
    const float* ncscale= (const float*)d_in[5];
    const float* q_w    = (const float*)d_in[6];
    const float* kv_w   = (const float*)d_in[7];
    const float* hscale = (const float*)d_in[8];
    const float* out_w  = (const float*)d_in[9];
    float* out = (float*)d_out;

    float *xn, *xc, *q, *kv, *o;
    cudaGetSymbolAddress((void**)&xn, g_xn);
    cudaGetSymbolAddress((void**)&xc, g_xc);
    cudaGetSymbolAddress((void**)&q,  g_q);
    cudaGetSymbolAddress((void**)&kv, g_kv);
    cudaGetSymbolAddress((void**)&o,  g_o);

    rmsnorm_k<<<NROWS, 256>>>(x, nscale, xn);
    rmsnorm_k<<<NROWS, 256>>>(x_cross, ncscale, xc);

    gemm_tf32<false><<<dim3(DMODEL/128,   NROWS/128), 256>>>(xn, q_w,  nullptr, q,  NROWS, DMODEL,   DMODEL);
    gemm_tf32<false><<<dim3(2*DMODEL/128, NROWS/128), 256>>>(xc, kv_w, nullptr, kv, NROWS, 2*DMODEL, DMODEL);

    qkprep_k<<<NROWS*NH/4, 256>>>(q,  pos,  hscale, DMODEL);
    qkprep_k<<<NROWS*NH/4, 256>>>(kv, posc, hscale, 2*DMODEL);

    attn_tf32<<<dim3(NL/64, NH, NB), 128>>>(q, kv, o);

    gemm_tf32<true><<<dim3(DMODEL/128, NROWS/128), 256>>>(o, out_w, x, out, NROWS, DMODEL, DMODEL);
}

// round 3
// speedup vs baseline: 7.3633x; 2.6005x over previous
#include <cuda_runtime.h>
#include <cuda_bf16.h>
#include <math.h>

#define NB 2
#define NL 2048
#define NLC 2048
#define NH 16
#define DMODEL 1024
#define NROWS (NB*NL)

typedef __nv_bfloat16 bf16;

// ---------------- scratch ----------------
__device__ bf16  g_xnb[NROWS*DMODEL];
__device__ bf16  g_xcb[NROWS*DMODEL];
__device__ bf16  g_wq [DMODEL*DMODEL];
__device__ bf16  g_wkv[2*DMODEL*DMODEL];
__device__ bf16  g_wout[DMODEL*DMODEL];
__device__ float g_q32[NROWS*DMODEL];
__device__ float g_kv32[NROWS*2*DMODEL];
__device__ bf16  g_qb[NROWS*DMODEL];
__device__ bf16  g_kb[NROWS*DMODEL];
__device__ bf16  g_vb[NROWS*DMODEL];
__device__ bf16  g_ob[NROWS*DMODEL];

// ---------------- PTX helpers ----------------
__device__ __forceinline__ void cp16(void* s, const void* g) {
    unsigned sa = (unsigned)__cvta_generic_to_shared(s);
    asm volatile("cp.async.cg.shared.global [%0], [%1], 16;\n" :: "r"(sa), "l"(g));
}
#define CP_COMMIT() asm volatile("cp.async.commit_group;\n")
#define CP_WAIT0()  asm volatile("cp.async.wait_group 0;\n")

__device__ __forceinline__ void ldmx4(unsigned* r, const void* p) {
    unsigned sa = (unsigned)__cvta_generic_to_shared(p);
    asm volatile("ldmatrix.sync.aligned.m8n8.x4.shared.b16 {%0,%1,%2,%3}, [%4];"
                 : "=r"(r[0]), "=r"(r[1]), "=r"(r[2]), "=r"(r[3]) : "r"(sa));
}
__device__ __forceinline__ void ldmx4t(unsigned* r, const void* p) {
    unsigned sa = (unsigned)__cvta_generic_to_shared(p);
    asm volatile("ldmatrix.sync.aligned.m8n8.x4.trans.shared.b16 {%0,%1,%2,%3}, [%4];"
                 : "=r"(r[0]), "=r"(r[1]), "=r"(r[2]), "=r"(r[3]) : "r"(sa));
}
__device__ __forceinline__ void mma16(float* d, const unsigned* a, const unsigned* b) {
    asm("mma.sync.aligned.m16n8k16.row.col.f32.bf16.bf16.f32 "
        "{%0,%1,%2,%3},{%4,%5,%6,%7},{%8,%9},{%0,%1,%2,%3};"
        : "+f"(d[0]), "+f"(d[1]), "+f"(d[2]), "+f"(d[3])
        : "r"(a[0]), "r"(a[1]), "r"(a[2]), "r"(a[3]), "r"(b[0]), "r"(b[1]));
}
// smem elem index for [row][64-wide bf16 row], SW128 at 16B (8-elem) chunk granularity
__device__ __forceinline__ int swz(int row, int ch) {
    return row*64 + ((ch ^ (row & 7)) << 3);
}

// ---------------- fp32 -> bf16 convert ----------------
__global__ __launch_bounds__(256) void f2b_k(const float* __restrict__ src,
                                             bf16* __restrict__ dst, int n4) {
    int i = blockIdx.x*256 + threadIdx.x;
    if (i >= n4) return;
    float4 v = ((const float4*)src)[i];
    ((__nv_bfloat162*)dst)[2*i]   = __floats2bfloat162_rn(v.x, v.y);
    ((__nv_bfloat162*)dst)[2*i+1] = __floats2bfloat162_rn(v.z, v.w);
}

// ---------------- RMS norm (fp32 in, bf16 out) ----------------
__global__ __launch_bounds__(256) void rmsnorm_k(const float* __restrict__ x,
                                                 const float* __restrict__ scale,
                                                 bf16* __restrict__ out) {
    int row = blockIdx.x;
    const float* xr = x + (size_t)row * DMODEL;
    float ss = 0.f;
    #pragma unroll
    for (int i = threadIdx.x; i < DMODEL; i += 256) { float v = xr[i]; ss += v*v; }
    __shared__ float red[256];
    red[threadIdx.x] = ss;
    __syncthreads();
    #pragma unroll
    for (int s = 128; s > 0; s >>= 1) {
        if (threadIdx.x < s) red[threadIdx.x] += red[threadIdx.x + s];
        __syncthreads();
    }
    float inv = rsqrtf(red[0] * (1.0f/DMODEL) + 1e-6f);
    #pragma unroll
    for (int i = threadIdx.x; i < DMODEL; i += 256)
        out[(size_t)row*DMODEL + i] = __float2bfloat16_rn(xr[i] * scale[i] * inv);
}

// ---------------- bf16 tensor-core GEMM: C[M,N](f32) = A[M,K] @ B[N,K]^T (+skip) ----------
// 128x64 block, BK=64, 2-stage cp.async, 8 warps (4x2), warp tile 32x32.
template<bool ADD>
__global__ __launch_bounds__(256) void gemm_bf16(const bf16* __restrict__ A,
                                                 const bf16* __restrict__ B,
                                                 const float* __restrict__ skip,
                                                 float* __restrict__ C,
                                                 int M, int N, int K) {
    __shared__ __align__(16) bf16 As[2][128*64];
    __shared__ __align__(16) bf16 Bs[2][64*64];
    const int bm = blockIdx.y*128, bn = blockIdx.x*64;
    const int tid = threadIdx.x, w = tid >> 5, lane = tid & 31;
    const int g = lane >> 2, t4 = lane & 3;
    const int wm = (w >> 1)*32, wn = (w & 1)*32;
    const int part = lane >> 3, l7 = lane & 7;

    float acc[2][4][4] = {};
    const int T = K >> 6;

    auto load_tile = [&](int kt, int st) {
        int k0 = kt << 6;
        #pragma unroll
        for (int i = 0; i < 4; i++) {
            int c = tid + i*256, row = c >> 3, ch = c & 7;
            cp16(&As[st][swz(row, ch)], A + (size_t)(bm + row)*K + k0 + ch*8);
        }
        #pragma unroll
        for (int i = 0; i < 2; i++) {
            int c = tid + i*256, row = c >> 3, ch = c & 7;
            cp16(&Bs[st][swz(row, ch)], B + (size_t)(bn + row)*K + k0 + ch*8);
        }
    };

    load_tile(0, 0);
    CP_COMMIT();

    for (int kt = 0; kt < T; kt++) {
        CP_WAIT0();
        __syncthreads();
        if (kt + 1 < T) { load_tile(kt+1, (kt+1)&1); CP_COMMIT(); }
        int st = kt & 1;
        #pragma unroll
        for (int ks = 0; ks < 4; ks++) {
            unsigned af[2][4], bfr[4][2];
            #pragma unroll
            for (int mt = 0; mt < 2; mt++) {
                int row = wm + mt*16 + (part & 1)*8 + l7;
                int ch  = ks*2 + (part >> 1);
                ldmx4(af[mt], &As[st][swz(row, ch)]);
            }
            #pragma unroll
            for (int p = 0; p < 2; p++) {
                int row = wn + p*16 + (part >> 1)*8 + l7;
                int ch  = ks*2 + (part & 1);
                unsigned r4[4];
                ldmx4(r4, &Bs[st][swz(row, ch)]);
                bfr[2*p][0] = r4[0]; bfr[2*p][1] = r4[1];
                bfr[2*p+1][0] = r4[2]; bfr[2*p+1][1] = r4[3];
            }
            #pragma unroll
            for (int mt = 0; mt < 2; mt++)
                #pragma unroll
                for (int nt = 0; nt < 4; nt++)
                    mma16(acc[mt][nt], af[mt], bfr[nt]);
        }
    }

    #pragma unroll
    for (int mt = 0; mt < 2; mt++) {
        size_t r0 = bm + wm + mt*16 + g, r1 = r0 + 8;
        #pragma unroll
        for (int nt = 0; nt < 4; nt++) {
            size_t cc = bn + wn + nt*8 + 2*t4;
            float2 v0 = make_float2(acc[mt][nt][0], acc[mt][nt][1]);
            float2 v1 = make_float2(acc[mt][nt][2], acc[mt][nt][3]);
            if (ADD) {
                float2 s0 = *(const float2*)&skip[r0*N + cc];
                float2 s1 = *(const float2*)&skip[r1*N + cc];
                v0.x += s0.x; v0.y += s0.y; v1.x += s1.x; v1.y += s1.y;
            }
            *(float2*)&C[r0*N + cc] = v0;
            *(float2*)&C[r1*N + cc] = v1;
        }
    }
}

// ---------------- cosine scale + RoPE: fp32 src -> bf16 dst; optional v convert -------
__global__ __launch_bounds__(256) void qkprep_k(const float* __restrict__ src, int sstride,
                                                const float* __restrict__ pos,
                                                const float* __restrict__ head_scale,
                                                bf16* __restrict__ dst,
                                                const float* __restrict__ vsrc,
                                                bf16* __restrict__ vdst) {
    const int g  = threadIdx.x >> 6;
    const int d  = threadIdx.x & 63;
    const int gv = blockIdx.x*4 + g;
    const int row = gv >> 4;
    const int h   = gv & 15;
    size_t sidx = (size_t)row*sstride + h*64 + d;
    size_t didx = (size_t)row*DMODEL + h*64 + d;
    float v = src[sidx];

    if (vdst) vdst[didx] = __float2bfloat16_rn(vsrc[sidx]);

    __shared__ float sv[4][64];
    __shared__ float sred[4][64];
    sv[g][d] = v;
    sred[g][d] = v*v;
    __syncthreads();
    #pragma unroll
    for (int s = 32; s > 0; s >>= 1) {
        if (d < s) sred[g][d] += sred[g][d + s];
        __syncthreads();
    }
    float cs = sqrtf(head_scale[h]) * rsqrtf(sred[g][0] + 1e-6f);

    float out;
    if (d < 60) {
        int i = (d < 30) ? d : d - 30;
        int a = i / 10, j = i % 10;
        float fr = 3.14159265358979323846f * exp10f((float)(j*16 + h) * (1.0f/160.0f));
        float th = pos[(size_t)row*3 + a] * fr;
        float sn, c;
        sincosf(th, &sn, &c);
        if (d < 30) out = cs * (v*c - sv[g][d + 30]*sn);
        else        out = cs * (v*c + sv[g][d - 30]*sn);
    } else {
        out = cs * v;
    }
    dst[didx] = __float2bfloat16_rn(out);
}

// ---------------- flash attention, bf16 mma ----------------
// 64x64 q-tile, 4 warps (16 rows each), K/V double-buffered cp.async, 48KB smem.
__global__ __launch_bounds__(128) void attn_bf16(const bf16* __restrict__ Q,
                                                 const bf16* __restrict__ Kb,
                                                 const bf16* __restrict__ Vb,
                                                 bf16* __restrict__ O) {
    __shared__ __align__(16) bf16 Qs[64*64];
    __shared__ __align__(16) bf16 Ps[64*64];
    __shared__ __align__(16) bf16 Ks[2][64*64];
    __shared__ __align__(16) bf16 Vs[2][64*64];
    const int b = blockIdx.z, h = blockIdx.y, m0 = blockIdx.x*64;
    const int tid = threadIdx.x, w = tid >> 5, lane = tid & 31;
    const int g = lane >> 2, t4 = lane & 3;
    const int part = lane >> 3, l7 = lane & 7;

    auto load_kv = [&](int kt, int st) {
        int n0 = kt << 6;
        #pragma unroll
        for (int i = 0; i < 4; i++) {
            int c = tid + i*128, row = c >> 3, ch = c & 7;
            size_t base = ((size_t)(b*NLC + n0 + row)*NH + h)*64 + ch*8;
            cp16(&Ks[st][swz(row, ch)], Kb + base);
            cp16(&Vs[st][swz(row, ch)], Vb + base);
        }
    };

    // prologue: Q + KV(0), one group
    #pragma unroll
    for (int i = 0; i < 4; i++) {
        int c = tid + i*128, row = c >> 3, ch = c & 7;
        cp16(&Qs[swz(row, ch)], Q + ((size_t)(b*NL + m0 + row)*NH + h)*64 + ch*8);
    }
    load_kv(0, 0);
    CP_COMMIT();

    float o_acc[8][4] = {};
    float rm0 = -INFINITY, rm1 = -INFINITY, rs0 = 0.f, rs1 = 0.f;

    const int T = NLC/64;
    for (int kt = 0; kt < T; kt++) {
        CP_WAIT0();
        __syncthreads();
        if (kt + 1 < T) { load_kv(kt+1, (kt+1)&1); CP_COMMIT(); }
        int st = kt & 1;

        // S = Q K^T : 16 rows x 64 keys per warp
        float s[8][4] = {};
        #pragma unroll
        for (int ks = 0; ks < 4; ks++) {
            unsigned aq[4];
            {
                int row = 16*w + (part & 1)*8 + l7;
                int ch  = ks*2 + (part >> 1);
                ldmx4(aq, &Qs[swz(row, ch)]);
            }
            #pragma unroll
            for (int p = 0; p < 4; p++) {
                int row = p*16 + (part >> 1)*8 + l7;
                int ch  = ks*2 + (part & 1);
                unsigned r4[4];
                ldmx4(r4, &Ks[st][swz(row, ch)]);
                unsigned b0[2] = {r4[0], r4[1]}, b1[2] = {r4[2], r4[3]};
                mma16(s[2*p],   aq, b0);
                mma16(s[2*p+1], aq, b1);
            }
        }

        // online softmax: rows r0 = 16w+g, r1 = r0+8
        float mx0 = -INFINITY, mx1 = -INFINITY;
        #pragma unroll
        for (int nt = 0; nt < 8; nt++) {
            mx0 = fmaxf(mx0, fmaxf(s[nt][0], s[nt][1]));
            mx1 = fmaxf(mx1, fmaxf(s[nt][2], s[nt][3]));
        }
        #pragma unroll
        for (int off = 1; off <= 2; off <<= 1) {
            mx0 = fmaxf(mx0, __shfl_xor_sync(0xffffffffu, mx0, off));
            mx1 = fmaxf(mx1, __shfl_xor_sync(0xffffffffu, mx1, off));
        }
        float mn0 = fmaxf(rm0, mx0), mn1 = fmaxf(rm1, mx1);
        float cr0 = __expf(rm0 - mn0), cr1 = __expf(rm1 - mn1);
        rm0 = mn0; rm1 = mn1;
        float ls0 = 0.f, ls1 = 0.f;
        #pragma unroll
        for (int nt = 0; nt < 8; nt++) {
            s[nt][0] = __expf(s[nt][0] - mn0);
            s[nt][1] = __expf(s[nt][1] - mn0);
            s[nt][2] = __expf(s[nt][2] - mn1);
            s[nt][3] = __expf(s[nt][3] - mn1);
            ls0 += s[nt][0] + s[nt][1];
            ls1 += s[nt][2] + s[nt][3];
        }
        #pragma unroll
        for (int off = 1; off <= 2; off <<= 1) {
            ls0 += __shfl_xor_sync(0xffffffffu, ls0, off);
            ls1 += __shfl_xor_sync(0xffffffffu, ls1, off);
        }
        rs0 = rs0*cr0 + ls0;
        rs1 = rs1*cr1 + ls1;
        #pragma unroll
        for (int nt = 0; nt < 8; nt++) {
            o_acc[nt][0] *= cr0; o_acc[nt][1] *= cr0;
            o_acc[nt][2] *= cr1; o_acc[nt][3] *= cr1;
        }

        // store P (bf16) into this warp's own 16 rows
        {
            int r0 = 16*w + g, r1 = r0 + 8;
            #pragma unroll
            for (int nt = 0; nt < 8; nt++) {
                int idx0 = r0*64 + ((nt ^ (r0 & 7)) << 3) + 2*t4;
                int idx1 = r1*64 + ((nt ^ (r1 & 7)) << 3) + 2*t4;
                *(__nv_bfloat162*)&Ps[idx0] = __floats2bfloat162_rn(s[nt][0], s[nt][1]);
                *(__nv_bfloat162*)&Ps[idx1] = __floats2bfloat162_rn(s[nt][2], s[nt][3]);
            }
        }
        __syncwarp();

        // O += P V
        #pragma unroll
        for (int ks = 0; ks < 4; ks++) {
            unsigned ap[4];
            {
                int row = 16*w + (part & 1)*8 + l7;
                int ch  = ks*2 + (part >> 1);
                ldmx4(ap, &Ps[swz(row, ch)]);
            }
            #pragma unroll
            for (int p = 0; p < 4; p++) {
                int row = ks*16 + (part & 1)*8 + l7;
                int ch  = p*2 + (part >> 1);
                unsigned r4[4];
                ldmx4t(r4, &Vs[st][swz(row, ch)]);
                unsigned b0[2] = {r4[0], r4[1]}, b1[2] = {r4[2], r4[3]};
                mma16(o_acc[2*p],   ap, b0);
                mma16(o_acc[2*p+1], ap, b1);
            }
        }
    }

    float inv0 = 1.f / rs0, inv1 = 1.f / rs1;
    size_t r0 = m0 + 16*w + g, r1 = r0 + 8;
    #pragma unroll
    for (int nt = 0; nt < 8; nt++) {
        size_t cc = nt*8 + 2*t4;
        *(__nv_bfloat162*)&O[((size_t)(b*NL + r0)*NH + h)*64 + cc] =
            __floats2bfloat162_rn(o_acc[nt][0]*inv0, o_acc[nt][1]*inv0);
        *(__nv_bfloat162*)&O[((size_t)(b*NL + r1)*NH + h)*64 + cc] =
            __floats2bfloat162_rn(o_acc[nt][2]*inv1, o_acc[nt][3]*inv1);
    }
}

// ---------------- launcher ----------------
extern "C" void kernel_launch(void* const* d_in, const int* in_sizes, int n_in,
                              void* d_out, int out_size) {
    const float* x      = (const float*)d_in[0];
    const float* pos    = (const float*)d_in[1];
    const float* x_cross= (const float*)d_in[2];
    const float* posc   = (const float*)d_in[3];
    const float* nscale = (const float*)d_in[4];
    const float* ncscale= (const float*)d_in[5];
    const float* q_w    = (const float*)d_in[6];
    const float* kv_w   = (const float*)d_in[7];
    const float* hscale = (const float*)d_in[8];
    const float* out_w  = (const float*)d_in[9];
    float* out = (float*)d_out;

    bf16 *xnb, *xcb, *wq, *wkv, *wout, *qb, *kb, *vb, *ob;
    float *q32, *kv32;
    cudaGetSymbolAddress((void**)&xnb, g_xnb);
    cudaGetSymbolAddress((void**)&xcb, g_xcb);
    cudaGetSymbolAddress((void**)&wq,  g_wq);
    cudaGetSymbolAddress((void**)&wkv, g_wkv);
    cudaGetSymbolAddress((void**)&wout,g_wout);
    cudaGetSymbolAddress((void**)&q32, g_q32);
    cudaGetSymbolAddress((void**)&kv32,g_kv32);
    cudaGetSymbolAddress((void**)&qb,  g_qb);
    cudaGetSymbolAddress((void**)&kb,  g_kb);
    cudaGetSymbolAddress((void**)&vb,  g_vb);
    cudaGetSymbolAddress((void**)&ob,  g_ob);

    // weight converts
    f2b_k<<<(DMODEL*DMODEL/4 + 255)/256, 256>>>(q_w,  wq,  DMODEL*DMODEL/4);
    f2b_k<<<(2*DMODEL*DMODEL/4 + 255)/256, 256>>>(kv_w, wkv, 2*DMODEL*DMODEL/4);
    f2b_k<<<(DMODEL*DMODEL/4 + 255)/256, 256>>>(out_w, wout, DMODEL*DMODEL/4);

    rmsnorm_k<<<NROWS, 256>>>(x, nscale, xnb);
    rmsnorm_k<<<NROWS, 256>>>(x_cross, ncscale, xcb);

    gemm_bf16<false><<<dim3(DMODEL/64,   NROWS/128), 256>>>(xnb, wq,  nullptr, q32,  NROWS, DMODEL,   DMODEL);
    gemm_bf16<false><<<dim3(2*DMODEL/64, NROWS/128), 256>>>(xcb, wkv, nullptr, kv32, NROWS, 2*DMODEL, DMODEL);

    qkprep_k<<<NROWS*NH/4, 256>>>(q32,  DMODEL,   pos,  hscale, qb, nullptr, nullptr);
    qkprep_k<<<NROWS*NH/4, 256>>>(kv32, 2*DMODEL, posc, hscale, kb, kv32 + DMODEL, vb);

    attn_bf16<<<dim3(NL/64, NH, NB), 128>>>(qb, kb, vb, ob);

    gemm_bf16<true><<<dim3(DMODEL/64, NROWS/128), 256>>>(ob, wout, x, out, NROWS, DMODEL, DMODEL);
}

// round 5
// speedup vs baseline: 7.4574x; 1.0128x over previous
#include <cuda_runtime.h>
#include <cuda_bf16.h>
#include <math.h>
#include <stdint.h>

#define NB 2
#define NL 2048
#define NLC 2048
#define NH 16
#define DMODEL 1024
#define NROWS (NB*NL)

typedef __nv_bfloat16 bf16;

// ---------------- scratch ----------------
__device__ bf16 g_xnb[NROWS*DMODEL];
__device__ bf16 g_xcb[NROWS*DMODEL];
__device__ bf16 g_wq [DMODEL*DMODEL];
__device__ bf16 g_wkv[2*DMODEL*DMODEL];
__device__ bf16 g_wout[DMODEL*DMODEL];
__device__ bf16 g_qpre[NROWS*DMODEL];
__device__ bf16 g_kvb [NROWS*2*DMODEL];
__device__ bf16 g_qb[NROWS*DMODEL];
__device__ bf16 g_kb[NROWS*DMODEL];
__device__ bf16 g_ob[NROWS*DMODEL];

// ---------------- PTX helpers ----------------
__device__ __forceinline__ uint32_t s2u(const void* p) {
    return (uint32_t)__cvta_generic_to_shared(p);
}
__device__ __forceinline__ void cp16(void* s, const void* g) {
    asm volatile("cp.async.cg.shared.global [%0], [%1], 16;\n" :: "r"(s2u(s)), "l"(g));
}
#define CP_COMMIT() asm volatile("cp.async.commit_group;\n")
#define CP_WAIT0()  asm volatile("cp.async.wait_group 0;\n")
#define CP_WAIT1()  asm volatile("cp.async.wait_group 1;\n")

__device__ __forceinline__ void ldmx4(unsigned* r, const void* p) {
    asm volatile("ldmatrix.sync.aligned.m8n8.x4.shared.b16 {%0,%1,%2,%3}, [%4];"
                 : "=r"(r[0]), "=r"(r[1]), "=r"(r[2]), "=r"(r[3]) : "r"(s2u(p)));
}
__device__ __forceinline__ void ldmx4t(unsigned* r, const void* p) {
    asm volatile("ldmatrix.sync.aligned.m8n8.x4.trans.shared.b16 {%0,%1,%2,%3}, [%4];"
                 : "=r"(r[0]), "=r"(r[1]), "=r"(r[2]), "=r"(r[3]) : "r"(s2u(p)));
}
__device__ __forceinline__ void mma16(float* d, const unsigned* a, const unsigned* b) {
    asm("mma.sync.aligned.m16n8k16.row.col.f32.bf16.bf16.f32 "
        "{%0,%1,%2,%3},{%4,%5,%6,%7},{%8,%9},{%0,%1,%2,%3};"
        : "+f"(d[0]), "+f"(d[1]), "+f"(d[2]), "+f"(d[3])
        : "r"(a[0]), "r"(a[1]), "r"(a[2]), "r"(a[3]), "r"(b[0]), "r"(b[1]));
}
__device__ __forceinline__ int swz(int row, int ch) {   // elem idx, 64-elem (128B) rows
    return row*64 + ((ch ^ (row & 7)) << 3);
}
__device__ __forceinline__ unsigned packbf(float a, float b) {
    __nv_bfloat162 h = __floats2bfloat162_rn(a, b);
    return *(unsigned*)&h;
}

// ---------------- fp32 -> bf16 convert ----------------
__global__ __launch_bounds__(256) void f2b_k(const float* __restrict__ src,
                                             bf16* __restrict__ dst, int n4) {
    int i = blockIdx.x*256 + threadIdx.x;
    if (i >= n4) return;
    float4 v = ((const float4*)src)[i];
    ((__nv_bfloat162*)dst)[2*i]   = __floats2bfloat162_rn(v.x, v.y);
    ((__nv_bfloat162*)dst)[2*i+1] = __floats2bfloat162_rn(v.z, v.w);
}

// ---------------- RMS norm (vectorized) ----------------
__global__ __launch_bounds__(256) void rmsnorm_k(const float* __restrict__ x,
                                                 const float* __restrict__ scale,
                                                 bf16* __restrict__ out) {
    int row = blockIdx.x, tid = threadIdx.x;
    float4 v = ((const float4*)(x + (size_t)row*DMODEL))[tid];
    float ss = v.x*v.x + v.y*v.y + v.z*v.z + v.w*v.w;
    #pragma unroll
    for (int o = 16; o; o >>= 1) ss += __shfl_xor_sync(0xffffffffu, ss, o);
    __shared__ float ws[8];
    if ((tid & 31) == 0) ws[tid >> 5] = ss;
    __syncthreads();
    float tot = ws[0]+ws[1]+ws[2]+ws[3]+ws[4]+ws[5]+ws[6]+ws[7];
    float inv = rsqrtf(tot * (1.0f/DMODEL) + 1e-6f);
    float4 sc = ((const float4*)scale)[tid];
    __nv_bfloat162 a = __floats2bfloat162_rn(v.x*sc.x*inv, v.y*sc.y*inv);
    __nv_bfloat162 b = __floats2bfloat162_rn(v.z*sc.z*inv, v.w*sc.w*inv);
    uint2 pk;
    pk.x = *(uint32_t*)&a; pk.y = *(uint32_t*)&b;
    ((uint2*)(out + (size_t)row*DMODEL))[tid] = pk;
}

// ---------------- bf16 mma GEMM: C[M,N] = A[M,K]@B[N,K]^T (+skip) ----------------
// 128x128 block, BK=64, 3-stage cp.async, 8 warps (2x4), warp tile 64x32.
#define GEMM_SMEM (6*16384)   // 3 stages x (A 16KB + B 16KB)

template<typename OutT, bool ADD>
__global__ __launch_bounds__(256, 1) void gemm_bf(const bf16* __restrict__ A,
                                                  const bf16* __restrict__ B,
                                                  const float* __restrict__ skip,
                                                  OutT* __restrict__ C,
                                                  int M, int N, int K) {
    extern __shared__ char sm[];
    const int bm = blockIdx.y*128, bn = blockIdx.x*128;
    const int tid = threadIdx.x, w = tid >> 5, lane = tid & 31;
    const int g = lane >> 2, t4 = lane & 3;
    const int part = lane >> 3, l7 = lane & 7;
    const int wm = (w >> 2)*64, wn = (w & 3)*32;

    float acc[4][4][4] = {};
    const int T = K >> 6;

    auto load_tile = [&](int kt) {
        int st = kt % 3;
        char* As = sm + st*16384;
        char* Bs = sm + 49152 + st*16384;
        int k0 = kt << 6;
        #pragma unroll
        for (int i = 0; i < 4; i++) {
            int c = tid + i*256, r = c >> 3, ch = c & 7;
            cp16(As + r*128 + ((ch ^ (r & 7)) << 4), A + (size_t)(bm + r)*K + k0 + ch*8);
            cp16(Bs + r*128 + ((ch ^ (r & 7)) << 4), B + (size_t)(bn + r)*K + k0 + ch*8);
        }
    };

    load_tile(0); CP_COMMIT();
    load_tile(1); CP_COMMIT();
    CP_WAIT1(); __syncthreads();

    for (int kt = 0; kt < T; kt++) {
        int st = kt % 3;
        const bf16* As = (const bf16*)(sm + st*16384);
        const bf16* Bs = (const bf16*)(sm + 49152 + st*16384);
        #pragma unroll
        for (int ks = 0; ks < 4; ks++) {
            unsigned af[4][4], bfr[4][2];
            #pragma unroll
            for (int mt = 0; mt < 4; mt++) {
                int row = wm + mt*16 + (part & 1)*8 + l7;
                int ch  = ks*2 + (part >> 1);
                ldmx4(af[mt], &As[swz(row, ch)]);
            }
            #pragma unroll
            for (int p = 0; p < 2; p++) {
                int row = wn + p*16 + (part >> 1)*8 + l7;
                int ch  = ks*2 + (part & 1);
                unsigned r4[4];
                ldmx4(r4, &Bs[swz(row, ch)]);
                bfr[2*p][0] = r4[0]; bfr[2*p][1] = r4[1];
                bfr[2*p+1][0] = r4[2]; bfr[2*p+1][1] = r4[3];
            }
            #pragma unroll
            for (int mt = 0; mt < 4; mt++)
                #pragma unroll
                for (int nt = 0; nt < 4; nt++)
                    mma16(acc[mt][nt], af[mt], bfr[nt]);
        }
        __syncthreads();
        if (kt + 2 < T) { load_tile(kt + 2); CP_COMMIT(); }
        if (kt + 1 < T) {
            if (kt + 2 < T) { CP_WAIT1(); } else { CP_WAIT0(); }
            __syncthreads();
        }
    }

    #pragma unroll
    for (int mt = 0; mt < 4; mt++) {
        size_t r0 = bm + wm + mt*16 + g, r1 = r0 + 8;
        #pragma unroll
        for (int nt = 0; nt < 4; nt++) {
            size_t cc = bn + wn + nt*8 + 2*t4;
            float2 v0 = make_float2(acc[mt][nt][0], acc[mt][nt][1]);
            float2 v1 = make_float2(acc[mt][nt][2], acc[mt][nt][3]);
            if (ADD) {
                float2 s0 = *(const float2*)&skip[r0*N + cc];
                float2 s1 = *(const float2*)&skip[r1*N + cc];
                v0.x += s0.x; v0.y += s0.y; v1.x += s1.x; v1.y += s1.y;
            }
            if (sizeof(OutT) == 4) {
                *(float2*)&((float*)C)[r0*N + cc] = v0;
                *(float2*)&((float*)C)[r1*N + cc] = v1;
            } else {
                *(unsigned*)&((bf16*)C)[r0*N + cc] = packbf(v0.x, v0.y);
                *(unsigned*)&((bf16*)C)[r1*N + cc] = packbf(v1.x, v1.y);
            }
        }
    }
}

// ---------------- cosine scale + 3-axis RoPE (bf16 in/out) ----------------
__global__ __launch_bounds__(256) void qkprep_k(const bf16* __restrict__ src, int sstride,
                                                const float* __restrict__ pos,
                                                const float* __restrict__ head_scale,
                                                bf16* __restrict__ dst) {
    const int g  = threadIdx.x >> 6;
    const int d  = threadIdx.x & 63;
    const int gv = blockIdx.x*4 + g;
    const int row = gv >> 4;
    const int h   = gv & 15;
    float v = __bfloat162float(src[(size_t)row*sstride + h*64 + d]);

    __shared__ float sv[4][64];
    __shared__ float sred[4][64];
    sv[g][d] = v;
    sred[g][d] = v*v;
    __syncthreads();
    #pragma unroll
    for (int s = 32; s > 0; s >>= 1) {
        if (d < s) sred[g][d] += sred[g][d + s];
        __syncthreads();
    }
    float cs = sqrtf(head_scale[h]) * rsqrtf(sred[g][0] + 1e-6f);

    float out;
    if (d < 60) {
        int i = (d < 30) ? d : d - 30;
        int a = i / 10, j = i % 10;
        float fr = 3.14159265358979323846f * exp10f((float)(j*16 + h) * (1.0f/160.0f));
        float th = pos[(size_t)row*3 + a] * fr;
        float sn, c;
        sincosf(th, &sn, &c);
        if (d < 30) out = cs * (v*c - sv[g][d + 30]*sn);
        else        out = cs * (v*c + sv[g][d - 30]*sn);
    } else {
        out = cs * v;
    }
    dst[(size_t)row*DMODEL + h*64 + d] = __float2bfloat16_rn(out);
}

// ---------------- flash attention, bf16 mma, register P, fixed max ----------------
// q-tile 128 (8 warps x 16 rows), key-tile 64, K/V double-buffered.
// Scores bounded by ||q||*||k|| = 10 (cosine-normalized, RoPE preserves norm) ->
// softmax with constant shift 10 (mathematically exact; softmax shift-invariant).
__global__ __launch_bounds__(256) void attn_bf16(const bf16* __restrict__ Q,
                                                 const bf16* __restrict__ Kb,
                                                 const bf16* __restrict__ KVb,
                                                 bf16* __restrict__ O) {
    __shared__ __align__(16) bf16 Qs[128*64];
    __shared__ __align__(16) bf16 Ks[2][64*64];
    __shared__ __align__(16) bf16 Vs[2][64*64];
    const int b = blockIdx.z, h = blockIdx.y, m0 = blockIdx.x*128;
    const int tid = threadIdx.x, w = tid >> 5, lane = tid & 31;
    const int g = lane >> 2, t4 = lane & 3;
    const int part = lane >> 3, l7 = lane & 7;

    auto load_kv = [&](int kt, int st) {
        int n0 = kt << 6;
        #pragma unroll
        for (int i = 0; i < 2; i++) {
            int c = tid + i*256, row = c >> 3, ch = c & 7;
            cp16(&Ks[st][swz(row, ch)],
                 Kb + ((size_t)(b*NLC + n0 + row)*NH + h)*64 + ch*8);
            cp16(&Vs[st][swz(row, ch)],
                 KVb + (size_t)(b*NLC + n0 + row)*(2*DMODEL) + DMODEL + h*64 + ch*8);
        }
    };

    #pragma unroll
    for (int i = 0; i < 4; i++) {
        int c = tid + i*256, row = c >> 3, ch = c & 7;
        cp16(&Qs[swz(row, ch)], Q + ((size_t)(b*NL + m0 + row)*NH + h)*64 + ch*8);
    }
    load_kv(0, 0);
    CP_COMMIT();
    load_kv(1, 1);
    CP_COMMIT();
    CP_WAIT1(); __syncthreads();

    // hoist Q fragments (loop-invariant)
    unsigned qf[4][4];
    #pragma unroll
    for (int ks = 0; ks < 4; ks++) {
        int row = 16*w + (part & 1)*8 + l7;
        int ch  = ks*2 + (part >> 1);
        ldmx4(qf[ks], &Qs[swz(row, ch)]);
    }

    float o_acc[8][4] = {};
    float rs0 = 0.f, rs1 = 0.f;

    const int T = NLC/64;
    for (int kt = 0; kt < T; kt++) {
        int st = kt & 1;

        // S = Q K^T : 16 rows x 64 keys per warp
        float s[8][4] = {};
        #pragma unroll
        for (int ks = 0; ks < 4; ks++) {
            #pragma unroll
            for (int p = 0; p < 4; p++) {
                int row = p*16 + (part >> 1)*8 + l7;
                int ch  = ks*2 + (part & 1);
                unsigned r4[4];
                ldmx4(r4, &Ks[st][swz(row, ch)]);
                mma16(s[2*p],   qf[ks], r4);
                mma16(s[2*p+1], qf[ks], r4 + 2);
            }
        }

        // softmax with fixed shift; accumulate partial row sums (reduced at end)
        #pragma unroll
        for (int nt = 0; nt < 8; nt++) {
            s[nt][0] = __expf(s[nt][0] - 10.0f);
            s[nt][1] = __expf(s[nt][1] - 10.0f);
            s[nt][2] = __expf(s[nt][2] - 10.0f);
            s[nt][3] = __expf(s[nt][3] - 10.0f);
            rs0 += s[nt][0] + s[nt][1];
            rs1 += s[nt][2] + s[nt][3];
        }

        // O += P V  (P fragments built in registers from S fragments)
        #pragma unroll
        for (int ks = 0; ks < 4; ks++) {
            unsigned ap[4];
            ap[0] = packbf(s[2*ks][0],   s[2*ks][1]);
            ap[1] = packbf(s[2*ks][2],   s[2*ks][3]);
            ap[2] = packbf(s[2*ks+1][0], s[2*ks+1][1]);
            ap[3] = packbf(s[2*ks+1][2], s[2*ks+1][3]);
            #pragma unroll
            for (int p = 0; p < 4; p++) {
                int row = ks*16 + (part & 1)*8 + l7;
                int ch  = p*2 + (part >> 1);
                unsigned r4[4];
                ldmx4t(r4, &Vs[st][swz(row, ch)]);
                mma16(o_acc[2*p],   ap, r4);
                mma16(o_acc[2*p+1], ap, r4 + 2);
            }
        }

        __syncthreads();   // all warps done reading stage st
        if (kt + 2 < T) { load_kv(kt + 2, st); CP_COMMIT(); }
        if (kt + 1 < T) {
            if (kt + 2 < T) { CP_WAIT1(); } else { CP_WAIT0(); }
            __syncthreads();
        }
    }

    // final row-sum reduction across the quad (sum is linear -> defer to end)
    #pragma unroll
    for (int off = 1; off <= 2; off <<= 1) {
        rs0 += __shfl_xor_sync(0xffffffffu, rs0, off);
        rs1 += __shfl_xor_sync(0xffffffffu, rs1, off);
    }
    float inv0 = 1.f / rs0, inv1 = 1.f / rs1;
    size_t r0 = m0 + 16*w + g, r1 = r0 + 8;
    #pragma unroll
    for (int nt = 0; nt < 8; nt++) {
        size_t cc = nt*8 + 2*t4;
        *(unsigned*)&O[((size_t)(b*NL + r0)*NH + h)*64 + cc] =
            packbf(o_acc[nt][0]*inv0, o_acc[nt][1]*inv0);
        *(unsigned*)&O[((size_t)(b*NL + r1)*NH + h)*64 + cc] =
            packbf(o_acc[nt][2]*inv1, o_acc[nt][3]*inv1);
    }
}

// ---------------- launcher ----------------
extern "C" void kernel_launch(void* const* d_in, const int* in_sizes, int n_in,
                              void* d_out, int out_size) {
    const float* x      = (const float*)d_in[0];
    const float* pos    = (const float*)d_in[1];
    const float* x_cross= (const float*)d_in[2];
    const float* posc   = (const float*)d_in[3];
    const float* nscale = (const float*)d_in[4];
    const float* ncscale= (const float*)d_in[5];
    const float* q_w    = (const float*)d_in[6];
    const float* kv_w   = (const float*)d_in[7];
    const float* hscale = (const float*)d_in[8];
    const float* out_w  = (const float*)d_in[9];
    float* out = (float*)d_out;

    bf16 *xnb, *xcb, *wq, *wkv, *wout, *qpre, *kvb, *qb, *kb, *ob;
    cudaGetSymbolAddress((void**)&xnb, g_xnb);
    cudaGetSymbolAddress((void**)&xcb, g_xcb);
    cudaGetSymbolAddress((void**)&wq,  g_wq);
    cudaGetSymbolAddress((void**)&wkv, g_wkv);
    cudaGetSymbolAddress((void**)&wout,g_wout);
    cudaGetSymbolAddress((void**)&qpre,g_qpre);
    cudaGetSymbolAddress((void**)&kvb, g_kvb);
    cudaGetSymbolAddress((void**)&qb,  g_qb);
    cudaGetSymbolAddress((void**)&kb,  g_kb);
    cudaGetSymbolAddress((void**)&ob,  g_ob);

    cudaFuncSetAttribute(gemm_bf<bf16,false>, cudaFuncAttributeMaxDynamicSharedMemorySize, GEMM_SMEM);
    cudaFuncSetAttribute(gemm_bf<float,true>, cudaFuncAttributeMaxDynamicSharedMemorySize, GEMM_SMEM);

    f2b_k<<<(DMODEL*DMODEL/4 + 255)/256, 256>>>(q_w,  wq,  DMODEL*DMODEL/4);
    f2b_k<<<(2*DMODEL*DMODEL/4 + 255)/256, 256>>>(kv_w, wkv, 2*DMODEL*DMODEL/4);
    f2b_k<<<(DMODEL*DMODEL/4 + 255)/256, 256>>>(out_w, wout, DMODEL*DMODEL/4);

    rmsnorm_k<<<NROWS, 256>>>(x, nscale, xnb);
    rmsnorm_k<<<NROWS, 256>>>(x_cross, ncscale, xcb);

    gemm_bf<bf16,false><<<dim3(DMODEL/128,   NROWS/128), 256, GEMM_SMEM>>>(xnb, wq,  nullptr, qpre, NROWS, DMODEL,   DMODEL);
    gemm_bf<bf16,false><<<dim3(2*DMODEL/128, NROWS/128), 256, GEMM_SMEM>>>(xcb, wkv, nullptr, kvb,  NROWS, 2*DMODEL, DMODEL);

    qkprep_k<<<NROWS*NH/4, 256>>>(qpre, DMODEL,   pos,  hscale, qb);
    qkprep_k<<<NROWS*NH/4, 256>>>(kvb,  2*DMODEL, posc, hscale, kb);

    attn_bf16<<<dim3(NL/128, NH, NB), 256>>>(qb, kb, kvb, ob);

    gemm_bf<float,true><<<dim3(DMODEL/128, NROWS/128), 256, GEMM_SMEM>>>(ob, wout, x, out, NROWS, DMODEL, DMODEL);
}

// round 6
// speedup vs baseline: 7.5125x; 1.0074x over previous
#include <cuda_runtime.h>
#include <cuda_bf16.h>
#include <math.h>
#include <stdint.h>

#define NB 2
#define NL 2048
#define NLC 2048
#define NH 16
#define DMODEL 1024
#define NROWS (NB*NL)

typedef __nv_bfloat16 bf16;

// ---------------- scratch ----------------
__device__ bf16 g_xnb[NROWS*DMODEL];
__device__ bf16 g_xcb[NROWS*DMODEL];
__device__ bf16 g_wq [DMODEL*DMODEL];
__device__ bf16 g_wkv[2*DMODEL*DMODEL];
__device__ bf16 g_wout[DMODEL*DMODEL];
__device__ bf16 g_qpre[NROWS*DMODEL];
__device__ bf16 g_kvb [NROWS*2*DMODEL];
__device__ bf16 g_qb[NROWS*DMODEL];
__device__ bf16 g_kb[NROWS*DMODEL];
__device__ bf16 g_ob[NROWS*DMODEL];

// ---------------- PTX helpers ----------------
__device__ __forceinline__ uint32_t s2u(const void* p) {
    return (uint32_t)__cvta_generic_to_shared(p);
}
__device__ __forceinline__ void cp16(void* s, const void* g) {
    asm volatile("cp.async.cg.shared.global [%0], [%1], 16;\n" :: "r"(s2u(s)), "l"(g));
}
#define CP_COMMIT() asm volatile("cp.async.commit_group;\n")
#define CP_WAIT0()  asm volatile("cp.async.wait_group 0;\n")
#define CP_WAIT1()  asm volatile("cp.async.wait_group 1;\n")
#define CP_WAIT2()  asm volatile("cp.async.wait_group 2;\n")

__device__ __forceinline__ void ldmx4(unsigned* r, const void* p) {
    asm volatile("ldmatrix.sync.aligned.m8n8.x4.shared.b16 {%0,%1,%2,%3}, [%4];"
                 : "=r"(r[0]), "=r"(r[1]), "=r"(r[2]), "=r"(r[3]) : "r"(s2u(p)));
}
__device__ __forceinline__ void ldmx4t(unsigned* r, const void* p) {
    asm volatile("ldmatrix.sync.aligned.m8n8.x4.trans.shared.b16 {%0,%1,%2,%3}, [%4];"
                 : "=r"(r[0]), "=r"(r[1]), "=r"(r[2]), "=r"(r[3]) : "r"(s2u(p)));
}
__device__ __forceinline__ void mma16(float* d, const unsigned* a, const unsigned* b) {
    asm("mma.sync.aligned.m16n8k16.row.col.f32.bf16.bf16.f32 "
        "{%0,%1,%2,%3},{%4,%5,%6,%7},{%8,%9},{%0,%1,%2,%3};"
        : "+f"(d[0]), "+f"(d[1]), "+f"(d[2]), "+f"(d[3])
        : "r"(a[0]), "r"(a[1]), "r"(a[2]), "r"(a[3]), "r"(b[0]), "r"(b[1]));
}
__device__ __forceinline__ int swz(int row, int ch) {   // elem idx, 64-elem (128B) rows
    return row*64 + ((ch ^ (row & 7)) << 3);
}
__device__ __forceinline__ unsigned packbf(float a, float b) {
    __nv_bfloat162 h = __floats2bfloat162_rn(a, b);
    return *(unsigned*)&h;
}

// ---------------- fp32 -> bf16 convert ----------------
__global__ __launch_bounds__(256) void f2b_k(const float* __restrict__ src,
                                             bf16* __restrict__ dst, int n4) {
    int i = blockIdx.x*256 + threadIdx.x;
    if (i >= n4) return;
    float4 v = ((const float4*)src)[i];
    ((__nv_bfloat162*)dst)[2*i]   = __floats2bfloat162_rn(v.x, v.y);
    ((__nv_bfloat162*)dst)[2*i+1] = __floats2bfloat162_rn(v.z, v.w);
}

// ---------------- RMS norm: warp per row, MLP=8 ----------------
__global__ __launch_bounds__(256) void rmsnorm_k(const float* __restrict__ x,
                                                 const float* __restrict__ scale,
                                                 bf16* __restrict__ out) {
    const int w = threadIdx.x >> 5, lane = threadIdx.x & 31;
    const size_t row = blockIdx.x*8 + w;
    const float4* xr = (const float4*)(x + row*DMODEL);
    const float4* sc = (const float4*)scale;
    float4 v[8];
    #pragma unroll
    for (int i = 0; i < 8; i++) v[i] = xr[lane + i*32];
    float ss = 0.f;
    #pragma unroll
    for (int i = 0; i < 8; i++)
        ss += v[i].x*v[i].x + v[i].y*v[i].y + v[i].z*v[i].z + v[i].w*v[i].w;
    #pragma unroll
    for (int o = 16; o; o >>= 1) ss += __shfl_xor_sync(0xffffffffu, ss, o);
    float inv = rsqrtf(ss * (1.0f/DMODEL) + 1e-6f);
    uint2* op = (uint2*)(out + row*DMODEL);
    #pragma unroll
    for (int i = 0; i < 8; i++) {
        float4 s = sc[lane + i*32];
        uint2 pk;
        pk.x = packbf(v[i].x*s.x*inv, v[i].y*s.y*inv);
        pk.y = packbf(v[i].z*s.z*inv, v[i].w*s.w*inv);
        op[lane + i*32] = pk;
    }
}

// ---------------- bf16 mma GEMM: C[M,N] = A[M,K]@B[N,K]^T (+skip) ----------------
// 128x128 block, BK=64, 3-stage cp.async, ONE barrier per k-iter, 8 warps.
#define GEMM_SMEM (3*32768)

template<typename OutT, bool ADD>
__global__ __launch_bounds__(256, 1) void gemm_bf(const bf16* __restrict__ A,
                                                  const bf16* __restrict__ B,
                                                  const float* __restrict__ skip,
                                                  OutT* __restrict__ C,
                                                  int M, int N, int K) {
    extern __shared__ char sm[];
    const int bm = blockIdx.y*128, bn = blockIdx.x*128;
    const int tid = threadIdx.x, w = tid >> 5, lane = tid & 31;
    const int g = lane >> 2, t4 = lane & 3;
    const int part = lane >> 3, l7 = lane & 7;
    const int wm = (w >> 2)*64, wn = (w & 3)*32;

    float acc[4][4][4] = {};
    const int T = K >> 6;

    auto load_tile = [&](int kt) {
        int st = kt % 3;
        char* As = sm + st*32768;
        char* Bs = As + 16384;
        int k0 = kt << 6;
        #pragma unroll
        for (int i = 0; i < 4; i++) {
            int c = tid + i*256, r = c >> 3, ch = c & 7;
            cp16(As + r*128 + ((ch ^ (r & 7)) << 4), A + (size_t)(bm + r)*K + k0 + ch*8);
            cp16(Bs + r*128 + ((ch ^ (r & 7)) << 4), B + (size_t)(bn + r)*K + k0 + ch*8);
        }
    };

    load_tile(0); CP_COMMIT();
    load_tile(1); CP_COMMIT();

    for (int kt = 0; kt < T; kt++) {
        if (kt + 1 < T) { CP_WAIT1(); } else { CP_WAIT0(); }
        __syncthreads();
        if (kt + 2 < T) { load_tile(kt + 2); CP_COMMIT(); }

        int st = kt % 3;
        const bf16* As = (const bf16*)(sm + st*32768);
        const bf16* Bs = (const bf16*)(sm + st*32768 + 16384);
        #pragma unroll
        for (int ks = 0; ks < 4; ks++) {
            unsigned af[4][4], bfr[4][2];
            #pragma unroll
            for (int mt = 0; mt < 4; mt++) {
                int row = wm + mt*16 + (part & 1)*8 + l7;
                int ch  = ks*2 + (part >> 1);
                ldmx4(af[mt], &As[swz(row, ch)]);
            }
            #pragma unroll
            for (int p = 0; p < 2; p++) {
                int row = wn + p*16 + (part >> 1)*8 + l7;
                int ch  = ks*2 + (part & 1);
                unsigned r4[4];
                ldmx4(r4, &Bs[swz(row, ch)]);
                bfr[2*p][0] = r4[0]; bfr[2*p][1] = r4[1];
                bfr[2*p+1][0] = r4[2]; bfr[2*p+1][1] = r4[3];
            }
            #pragma unroll
            for (int mt = 0; mt < 4; mt++)
                #pragma unroll
                for (int nt = 0; nt < 4; nt++)
                    mma16(acc[mt][nt], af[mt], bfr[nt]);
        }
    }

    #pragma unroll
    for (int mt = 0; mt < 4; mt++) {
        size_t r0 = bm + wm + mt*16 + g, r1 = r0 + 8;
        #pragma unroll
        for (int nt = 0; nt < 4; nt++) {
            size_t cc = bn + wn + nt*8 + 2*t4;
            float2 v0 = make_float2(acc[mt][nt][0], acc[mt][nt][1]);
            float2 v1 = make_float2(acc[mt][nt][2], acc[mt][nt][3]);
            if (ADD) {
                float2 s0 = *(const float2*)&skip[r0*N + cc];
                float2 s1 = *(const float2*)&skip[r1*N + cc];
                v0.x += s0.x; v0.y += s0.y; v1.x += s1.x; v1.y += s1.y;
            }
            if (sizeof(OutT) == 4) {
                *(float2*)&((float*)C)[r0*N + cc] = v0;
                *(float2*)&((float*)C)[r1*N + cc] = v1;
            } else {
                *(unsigned*)&((bf16*)C)[r0*N + cc] = packbf(v0.x, v0.y);
                *(unsigned*)&((bf16*)C)[r1*N + cc] = packbf(v1.x, v1.y);
            }
        }
    }
}

// ---------------- cosine scale + 3-axis RoPE (bf16 in/out), 1 barrier ------------
__global__ __launch_bounds__(256) void qkprep_k(const bf16* __restrict__ src, int sstride,
                                                const float* __restrict__ pos,
                                                const float* __restrict__ head_scale,
                                                bf16* __restrict__ dst) {
    const int g  = threadIdx.x >> 6;
    const int d  = threadIdx.x & 63;
    const int gv = blockIdx.x*4 + g;
    const int row = gv >> 4;
    const int h   = gv & 15;
    float v = __bfloat162float(src[(size_t)row*sstride + h*64 + d]);

    __shared__ float sv[4][64];
    __shared__ float wsum[4][2];
    sv[g][d] = v;
    float ss = v*v;
    #pragma unroll
    for (int o = 16; o; o >>= 1) ss += __shfl_xor_sync(0xffffffffu, ss, o);
    if ((d & 31) == 0) wsum[g][d >> 5] = ss;
    __syncthreads();
    float cs = sqrtf(head_scale[h]) * rsqrtf(wsum[g][0] + wsum[g][1] + 1e-6f);

    float out;
    if (d < 60) {
        int i = (d < 30) ? d : d - 30;
        int a = i / 10, j = i % 10;
        float fr = 3.14159265358979323846f * exp10f((float)(j*16 + h) * (1.0f/160.0f));
        float th = pos[(size_t)row*3 + a] * fr;
        float sn, c;
        sincosf(th, &sn, &c);
        if (d < 30) out = cs * (v*c - sv[g][d + 30]*sn);
        else        out = cs * (v*c + sv[g][d - 30]*sn);
    } else {
        out = cs * v;
    }
    dst[(size_t)row*DMODEL + h*64 + d] = __float2bfloat16_rn(out);
}

// ---------------- flash attention ----------------
// q-tile 128 (8 warps x 16 rows), key-tile 128 (two 64-key sub-steps),
// 3-stage cp.async, ONE barrier per tile. Fixed softmax shift (scores in [-10,10]).
#define ATT_SMEM (16384 + 3*32768)   // Qs + 3 x (K 16KB + V 16KB)

__global__ __launch_bounds__(256, 1) void attn_bf16(const bf16* __restrict__ Q,
                                                    const bf16* __restrict__ Kb,
                                                    const bf16* __restrict__ KVb,
                                                    bf16* __restrict__ O) {
    extern __shared__ char sm[];
    bf16* Qs = (bf16*)sm;
    const int b = blockIdx.z, h = blockIdx.y, m0 = blockIdx.x*128;
    const int tid = threadIdx.x, w = tid >> 5, lane = tid & 31;
    const int g = lane >> 2, t4 = lane & 3;
    const int part = lane >> 3, l7 = lane & 7;

    auto load_kv = [&](int kt) {
        int st = kt % 3;
        bf16* Ks = (bf16*)(sm + 16384 + st*32768);
        bf16* Vs = Ks + 8192;
        int n0 = kt << 7;
        #pragma unroll
        for (int i = 0; i < 4; i++) {
            int c = tid + i*256, row = c >> 3, ch = c & 7;
            cp16(&Ks[swz(row, ch)],
                 Kb + ((size_t)(b*NLC + n0 + row)*NH + h)*64 + ch*8);
            cp16(&Vs[swz(row, ch)],
                 KVb + (size_t)(b*NLC + n0 + row)*(2*DMODEL) + DMODEL + h*64 + ch*8);
        }
    };

    // prologue: Q (group0), KV0 (group1), KV1 (group2)
    #pragma unroll
    for (int i = 0; i < 4; i++) {
        int c = tid + i*256, row = c >> 3, ch = c & 7;
        cp16(&Qs[swz(row, ch)], Q + ((size_t)(b*NL + m0 + row)*NH + h)*64 + ch*8);
    }
    CP_COMMIT();
    load_kv(0); CP_COMMIT();
    load_kv(1); CP_COMMIT();

    CP_WAIT2();          // Q ready
    __syncthreads();
    unsigned qf[4][4];
    #pragma unroll
    for (int ks = 0; ks < 4; ks++) {
        int row = 16*w + (part & 1)*8 + l7;
        int ch  = ks*2 + (part >> 1);
        ldmx4(qf[ks], &Qs[swz(row, ch)]);
    }

    float o_acc[8][4] = {};
    float rs0 = 0.f, rs1 = 0.f;

    const int T = NLC/128;
    for (int kt = 0; kt < T; kt++) {
        if (kt + 1 < T) { CP_WAIT1(); } else { CP_WAIT0(); }
        __syncthreads();
        if (kt + 2 < T) { load_kv(kt + 2); CP_COMMIT(); }

        int st = kt % 3;
        const bf16* Ks = (const bf16*)(sm + 16384 + st*32768);
        const bf16* Vs = Ks + 8192;

        #pragma unroll
        for (int half = 0; half < 2; half++) {
            const int koff = half*64;
            // S = Q K^T : 16 rows x 64 keys
            float s[8][4] = {};
            #pragma unroll
            for (int ks = 0; ks < 4; ks++) {
                #pragma unroll
                for (int p = 0; p < 4; p++) {
                    int row = koff + p*16 + (part >> 1)*8 + l7;
                    int ch  = ks*2 + (part & 1);
                    unsigned r4[4];
                    ldmx4(r4, &Ks[swz(row, ch)]);
                    mma16(s[2*p],   qf[ks], r4);
                    mma16(s[2*p+1], qf[ks], r4 + 2);
                }
            }
            // softmax, fixed shift
            #pragma unroll
            for (int nt = 0; nt < 8; nt++) {
                s[nt][0] = __expf(s[nt][0] - 10.0f);
                s[nt][1] = __expf(s[nt][1] - 10.0f);
                s[nt][2] = __expf(s[nt][2] - 10.0f);
                s[nt][3] = __expf(s[nt][3] - 10.0f);
                rs0 += s[nt][0] + s[nt][1];
                rs1 += s[nt][2] + s[nt][3];
            }
            // O += P V
            #pragma unroll
            for (int ks = 0; ks < 4; ks++) {
                unsigned ap[4];
                ap[0] = packbf(s[2*ks][0],   s[2*ks][1]);
                ap[1] = packbf(s[2*ks][2],   s[2*ks][3]);
                ap[2] = packbf(s[2*ks+1][0], s[2*ks+1][1]);
                ap[3] = packbf(s[2*ks+1][2], s[2*ks+1][3]);
                #pragma unroll
                for (int p = 0; p < 4; p++) {
                    int row = koff + ks*16 + (part & 1)*8 + l7;
                    int ch  = p*2 + (part >> 1);
                    unsigned r4[4];
                    ldmx4t(r4, &Vs[swz(row, ch)]);
                    mma16(o_acc[2*p],   ap, r4);
                    mma16(o_acc[2*p+1], ap, r4 + 2);
                }
            }
        }
    }

    #pragma unroll
    for (int off = 1; off <= 2; off <<= 1) {
        rs0 += __shfl_xor_sync(0xffffffffu, rs0, off);
        rs1 += __shfl_xor_sync(0xffffffffu, rs1, off);
    }
    float inv0 = 1.f / rs0, inv1 = 1.f / rs1;
    size_t r0 = m0 + 16*w + g, r1 = r0 + 8;
    #pragma unroll
    for (int nt = 0; nt < 8; nt++) {
        size_t cc = nt*8 + 2*t4;
        *(unsigned*)&O[((size_t)(b*NL + r0)*NH + h)*64 + cc] =
            packbf(o_acc[nt][0]*inv0, o_acc[nt][1]*inv0);
        *(unsigned*)&O[((size_t)(b*NL + r1)*NH + h)*64 + cc] =
            packbf(o_acc[nt][2]*inv1, o_acc[nt][3]*inv1);
    }
}

// ---------------- launcher ----------------
extern "C" void kernel_launch(void* const* d_in, const int* in_sizes, int n_in,
                              void* d_out, int out_size) {
    const float* x      = (const float*)d_in[0];
    const float* pos    = (const float*)d_in[1];
    const float* x_cross= (const float*)d_in[2];
    const float* posc   = (const float*)d_in[3];
    const float* nscale = (const float*)d_in[4];
    const float* ncscale= (const float*)d_in[5];
    const float* q_w    = (const float*)d_in[6];
    const float* kv_w   = (const float*)d_in[7];
    const float* hscale = (const float*)d_in[8];
    const float* out_w  = (const float*)d_in[9];
    float* out = (float*)d_out;

    bf16 *xnb, *xcb, *wq, *wkv, *wout, *qpre, *kvb, *qb, *kb, *ob;
    cudaGetSymbolAddress((void**)&xnb, g_xnb);
    cudaGetSymbolAddress((void**)&xcb, g_xcb);
    cudaGetSymbolAddress((void**)&wq,  g_wq);
    cudaGetSymbolAddress((void**)&wkv, g_wkv);
    cudaGetSymbolAddress((void**)&wout,g_wout);
    cudaGetSymbolAddress((void**)&qpre,g_qpre);
    cudaGetSymbolAddress((void**)&kvb, g_kvb);
    cudaGetSymbolAddress((void**)&qb,  g_qb);
    cudaGetSymbolAddress((void**)&kb,  g_kb);
    cudaGetSymbolAddress((void**)&ob,  g_ob);

    cudaFuncSetAttribute(gemm_bf<bf16,false>, cudaFuncAttributeMaxDynamicSharedMemorySize, GEMM_SMEM);
    cudaFuncSetAttribute(gemm_bf<float,true>, cudaFuncAttributeMaxDynamicSharedMemorySize, GEMM_SMEM);
    cudaFuncSetAttribute(attn_bf16, cudaFuncAttributeMaxDynamicSharedMemorySize, ATT_SMEM);

    f2b_k<<<(DMODEL*DMODEL/4 + 255)/256, 256>>>(q_w,  wq,  DMODEL*DMODEL/4);
    f2b_k<<<(2*DMODEL*DMODEL/4 + 255)/256, 256>>>(kv_w, wkv, 2*DMODEL*DMODEL/4);
    f2b_k<<<(DMODEL*DMODEL/4 + 255)/256, 256>>>(out_w, wout, DMODEL*DMODEL/4);

    rmsnorm_k<<<NROWS/8, 256>>>(x, nscale, xnb);
    rmsnorm_k<<<NROWS/8, 256>>>(x_cross, ncscale, xcb);

    gemm_bf<bf16,false><<<dim3(DMODEL/128,   NROWS/128), 256, GEMM_SMEM>>>(xnb, wq,  nullptr, qpre, NROWS, DMODEL,   DMODEL);
    gemm_bf<bf16,false><<<dim3(2*DMODEL/128, NROWS/128), 256, GEMM_SMEM>>>(xcb, wkv, nullptr, kvb,  NROWS, 2*DMODEL, DMODEL);

    qkprep_k<<<NROWS*NH/4, 256>>>(qpre, DMODEL,   pos,  hscale, qb);
    qkprep_k<<<NROWS*NH/4, 256>>>(kvb,  2*DMODEL, posc, hscale, kb);

    attn_bf16<<<dim3(NL/128, NH, NB), 256, ATT_SMEM>>>(qb, kb, kvb, ob);

    gemm_bf<float,true><<<dim3(DMODEL/128, NROWS/128), 256, GEMM_SMEM>>>(ob, wout, x, out, NROWS, DMODEL, DMODEL);
}

// round 7
// speedup vs baseline: 8.1675x; 1.0872x over previous
#include <cuda_runtime.h>
#include <cuda_bf16.h>
#include <math.h>
#include <stdint.h>

#define NB 2
#define NL 2048
#define NLC 2048
#define NH 16
#define DMODEL 1024
#define NROWS (NB*NL)

typedef __nv_bfloat16 bf16;

// ---------------- scratch ----------------
__device__ bf16 g_xnb[NROWS*DMODEL];
__device__ bf16 g_xcb[NROWS*DMODEL];
__device__ bf16 g_wq [DMODEL*DMODEL];
__device__ bf16 g_wkv[2*DMODEL*DMODEL];
__device__ bf16 g_wout[DMODEL*DMODEL];
__device__ bf16 g_qpre[NROWS*DMODEL];
__device__ bf16 g_kvb [NROWS*2*DMODEL];
__device__ bf16 g_qb[NROWS*DMODEL];
__device__ bf16 g_kb[NROWS*DMODEL];
__device__ bf16 g_ob[NROWS*DMODEL];

// ---------------- PTX helpers ----------------
__device__ __forceinline__ uint32_t s2u(const void* p) {
    return (uint32_t)__cvta_generic_to_shared(p);
}
__device__ __forceinline__ void cp16(void* s, const void* g) {
    asm volatile("cp.async.cg.shared.global [%0], [%1], 16;\n" :: "r"(s2u(s)), "l"(g));
}
#define CP_COMMIT() asm volatile("cp.async.commit_group;\n")
#define CP_WAIT0()  asm volatile("cp.async.wait_group 0;\n")
#define CP_WAIT1()  asm volatile("cp.async.wait_group 1;\n")
#define CP_WAIT2()  asm volatile("cp.async.wait_group 2;\n")

__device__ __forceinline__ void ldmx4(unsigned* r, const void* p) {
    asm volatile("ldmatrix.sync.aligned.m8n8.x4.shared.b16 {%0,%1,%2,%3}, [%4];"
                 : "=r"(r[0]), "=r"(r[1]), "=r"(r[2]), "=r"(r[3]) : "r"(s2u(p)));
}
__device__ __forceinline__ void ldmx4t(unsigned* r, const void* p) {
    asm volatile("ldmatrix.sync.aligned.m8n8.x4.trans.shared.b16 {%0,%1,%2,%3}, [%4];"
                 : "=r"(r[0]), "=r"(r[1]), "=r"(r[2]), "=r"(r[3]) : "r"(s2u(p)));
}
__device__ __forceinline__ void mma16(float* d, const unsigned* a, const unsigned* b) {
    asm("mma.sync.aligned.m16n8k16.row.col.f32.bf16.bf16.f32 "
        "{%0,%1,%2,%3},{%4,%5,%6,%7},{%8,%9},{%0,%1,%2,%3};"
        : "+f"(d[0]), "+f"(d[1]), "+f"(d[2]), "+f"(d[3])
        : "r"(a[0]), "r"(a[1]), "r"(a[2]), "r"(a[3]), "r"(b[0]), "r"(b[1]));
}
__device__ __forceinline__ int swz(int row, int ch) {   // elem idx, 64-elem (128B) rows
    return row*64 + ((ch ^ (row & 7)) << 3);
}
__device__ __forceinline__ unsigned packbf(float a, float b) {
    __nv_bfloat162 h = __floats2bfloat162_rn(a, b);
    return *(unsigned*)&h;
}

// ---------------- fp32 -> bf16 convert ----------------
__global__ __launch_bounds__(256) void f2b_k(const float* __restrict__ src,
                                             bf16* __restrict__ dst, int n4) {
    int i = blockIdx.x*256 + threadIdx.x;
    if (i >= n4) return;
    float4 v = ((const float4*)src)[i];
    ((__nv_bfloat162*)dst)[2*i]   = __floats2bfloat162_rn(v.x, v.y);
    ((__nv_bfloat162*)dst)[2*i+1] = __floats2bfloat162_rn(v.z, v.w);
}

// ---------------- RMS norm: warp per row, MLP=8 ----------------
__global__ __launch_bounds__(256) void rmsnorm_k(const float* __restrict__ x,
                                                 const float* __restrict__ scale,
                                                 bf16* __restrict__ out) {
    const int w = threadIdx.x >> 5, lane = threadIdx.x & 31;
    const size_t row = blockIdx.x*8 + w;
    const float4* xr = (const float4*)(x + row*DMODEL);
    const float4* sc = (const float4*)scale;
    float4 v[8];
    #pragma unroll
    for (int i = 0; i < 8; i++) v[i] = xr[lane + i*32];
    float ss = 0.f;
    #pragma unroll
    for (int i = 0; i < 8; i++)
        ss += v[i].x*v[i].x + v[i].y*v[i].y + v[i].z*v[i].z + v[i].w*v[i].w;
    #pragma unroll
    for (int o = 16; o; o >>= 1) ss += __shfl_xor_sync(0xffffffffu, ss, o);
    float inv = rsqrtf(ss * (1.0f/DMODEL) + 1e-6f);
    uint2* op = (uint2*)(out + row*DMODEL);
    #pragma unroll
    for (int i = 0; i < 8; i++) {
        float4 s = sc[lane + i*32];
        uint2 pk;
        pk.x = packbf(v[i].x*s.x*inv, v[i].y*s.y*inv);
        pk.y = packbf(v[i].z*s.z*inv, v[i].w*s.w*inv);
        op[lane + i*32] = pk;
    }
}

// ---------------- bf16 mma GEMM: C[M,N] = A[M,K]@B[N,K]^T (+skip) ----------------
// 128x128 block, BK=64, 3-stage cp.async, ONE barrier per k-iter, 8 warps.
#define GEMM_SMEM (3*32768)

template<typename OutT, bool ADD>
__global__ __launch_bounds__(256, 1) void gemm_bf(const bf16* __restrict__ A,
                                                  const bf16* __restrict__ B,
                                                  const float* __restrict__ skip,
                                                  OutT* __restrict__ C,
                                                  int M, int N, int K) {
    extern __shared__ char sm[];
    const int bm = blockIdx.y*128, bn = blockIdx.x*128;
    const int tid = threadIdx.x, w = tid >> 5, lane = tid & 31;
    const int g = lane >> 2, t4 = lane & 3;
    const int part = lane >> 3, l7 = lane & 7;
    const int wm = (w >> 2)*64, wn = (w & 3)*32;

    float acc[4][4][4] = {};
    const int T = K >> 6;

    auto load_tile = [&](int kt) {
        int st = kt % 3;
        char* As = sm + st*32768;
        char* Bs = As + 16384;
        int k0 = kt << 6;
        #pragma unroll
        for (int i = 0; i < 4; i++) {
            int c = tid + i*256, r = c >> 3, ch = c & 7;
            cp16(As + r*128 + ((ch ^ (r & 7)) << 4), A + (size_t)(bm + r)*K + k0 + ch*8);
            cp16(Bs + r*128 + ((ch ^ (r & 7)) << 4), B + (size_t)(bn + r)*K + k0 + ch*8);
        }
    };

    load_tile(0); CP_COMMIT();
    load_tile(1); CP_COMMIT();

    for (int kt = 0; kt < T; kt++) {
        if (kt + 1 < T) { CP_WAIT1(); } else { CP_WAIT0(); }
        __syncthreads();
        if (kt + 2 < T) { load_tile(kt + 2); CP_COMMIT(); }

        int st = kt % 3;
        const bf16* As = (const bf16*)(sm + st*32768);
        const bf16* Bs = (const bf16*)(sm + st*32768 + 16384);
        #pragma unroll
        for (int ks = 0; ks < 4; ks++) {
            unsigned af[4][4], bfr[4][2];
            #pragma unroll
            for (int mt = 0; mt < 4; mt++) {
                int row = wm + mt*16 + (part & 1)*8 + l7;
                int ch  = ks*2 + (part >> 1);
                ldmx4(af[mt], &As[swz(row, ch)]);
            }
            #pragma unroll
            for (int p = 0; p < 2; p++) {
                int row = wn + p*16 + (part >> 1)*8 + l7;
                int ch  = ks*2 + (part & 1);
                unsigned r4[4];
                ldmx4(r4, &Bs[swz(row, ch)]);
                bfr[2*p][0] = r4[0]; bfr[2*p][1] = r4[1];
                bfr[2*p+1][0] = r4[2]; bfr[2*p+1][1] = r4[3];
            }
            #pragma unroll
            for (int mt = 0; mt < 4; mt++)
                #pragma unroll
                for (int nt = 0; nt < 4; nt++)
                    mma16(acc[mt][nt], af[mt], bfr[nt]);
        }
    }

    #pragma unroll
    for (int mt = 0; mt < 4; mt++) {
        size_t r0 = bm + wm + mt*16 + g, r1 = r0 + 8;
        #pragma unroll
        for (int nt = 0; nt < 4; nt++) {
            size_t cc = bn + wn + nt*8 + 2*t4;
            float2 v0 = make_float2(acc[mt][nt][0], acc[mt][nt][1]);
            float2 v1 = make_float2(acc[mt][nt][2], acc[mt][nt][3]);
            if (ADD) {
                float2 s0 = *(const float2*)&skip[r0*N + cc];
                float2 s1 = *(const float2*)&skip[r1*N + cc];
                v0.x += s0.x; v0.y += s0.y; v1.x += s1.x; v1.y += s1.y;
            }
            if (sizeof(OutT) == 4) {
                *(float2*)&((float*)C)[r0*N + cc] = v0;
                *(float2*)&((float*)C)[r1*N + cc] = v1;
            } else {
                *(unsigned*)&((bf16*)C)[r0*N + cc] = packbf(v0.x, v0.y);
                *(unsigned*)&((bf16*)C)[r1*N + cc] = packbf(v1.x, v1.y);
            }
        }
    }
}

// ---------------- cosine scale + 3-axis RoPE (bf16 in/out), 1 barrier ------------
__global__ __launch_bounds__(256) void qkprep_k(const bf16* __restrict__ src, int sstride,
                                                const float* __restrict__ pos,
                                                const float* __restrict__ head_scale,
                                                bf16* __restrict__ dst) {
    const int g  = threadIdx.x >> 6;
    const int d  = threadIdx.x & 63;
    const int gv = blockIdx.x*4 + g;
    const int row = gv >> 4;
    const int h   = gv & 15;
    float v = __bfloat162float(src[(size_t)row*sstride + h*64 + d]);

    __shared__ float sv[4][64];
    __shared__ float wsum[4][2];
    sv[g][d] = v;
    float ss = v*v;
    #pragma unroll
    for (int o = 16; o; o >>= 1) ss += __shfl_xor_sync(0xffffffffu, ss, o);
    if ((d & 31) == 0) wsum[g][d >> 5] = ss;
    __syncthreads();
    float cs = sqrtf(head_scale[h]) * rsqrtf(wsum[g][0] + wsum[g][1] + 1e-6f);

    float out;
    if (d < 60) {
        int i = (d < 30) ? d : d - 30;
        int a = i / 10, j = i % 10;
        float fr = 3.14159265358979323846f * exp10f((float)(j*16 + h) * (1.0f/160.0f));
        float th = pos[(size_t)row*3 + a] * fr;
        float sn, c;
        sincosf(th, &sn, &c);
        if (d < 30) out = cs * (v*c - sv[g][d + 30]*sn);
        else        out = cs * (v*c + sv[g][d - 30]*sn);
    } else {
        out = cs * v;
    }
    dst[(size_t)row*DMODEL + h*64 + d] = __float2bfloat16_rn(out);
}

// ---------------- flash attention ----------------
// q-tile 128 (8 warps x 16 rows), key-tile 128 (two 64-key sub-steps),
// 3-stage cp.async, ONE barrier per tile. Fixed softmax shift (scores in [-10,10]).
#define ATT_SMEM (16384 + 3*32768)   // Qs + 3 x (K 16KB + V 16KB)

__global__ __launch_bounds__(256, 1) void attn_bf16(const bf16* __restrict__ Q,
                                                    const bf16* __restrict__ Kb,
                                                    const bf16* __restrict__ KVb,
                                                    bf16* __restrict__ O) {
    extern __shared__ char sm[];
    bf16* Qs = (bf16*)sm;
    const int b = blockIdx.z, h = blockIdx.y, m0 = blockIdx.x*128;
    const int tid = threadIdx.x, w = tid >> 5, lane = tid & 31;
    const int g = lane >> 2, t4 = lane & 3;
    const int part = lane >> 3, l7 = lane & 7;

    auto load_kv = [&](int kt) {
        int st = kt % 3;
        bf16* Ks = (bf16*)(sm + 16384 + st*32768);
        bf16* Vs = Ks + 8192;
        int n0 = kt << 7;
        #pragma unroll
        for (int i = 0; i < 4; i++) {
            int c = tid + i*256, row = c >> 3, ch = c & 7;
            cp16(&Ks[swz(row, ch)],
                 Kb + ((size_t)(b*NLC + n0 + row)*NH + h)*64 + ch*8);
            cp16(&Vs[swz(row, ch)],
                 KVb + (size_t)(b*NLC + n0 + row)*(2*DMODEL) + DMODEL + h*64 + ch*8);
        }
    };

    #pragma unroll
    for (int i = 0; i < 4; i++) {
        int c = tid + i*256, row = c >> 3, ch = c & 7;
        cp16(&Qs[swz(row, ch)], Q + ((size_t)(b*NL + m0 + row)*NH + h)*64 + ch*8);
    }
    CP_COMMIT();
    load_kv(0); CP_COMMIT();
    load_kv(1); CP_COMMIT();

    CP_WAIT2();          // Q ready
    __syncthreads();
    unsigned qf[4][4];
    #pragma unroll
    for (int ks = 0; ks < 4; ks++) {
        int row = 16*w + (part & 1)*8 + l7;
        int ch  = ks*2 + (part >> 1);
        ldmx4(qf[ks], &Qs[swz(row, ch)]);
    }

    float o_acc[8][4] = {};
    float rs0 = 0.f, rs1 = 0.f;

    const int T = NLC/128;
    for (int kt = 0; kt < T; kt++) {
        if (kt + 1 < T) { CP_WAIT1(); } else { CP_WAIT0(); }
        __syncthreads();
        if (kt + 2 < T) { load_kv(kt + 2); CP_COMMIT(); }

        int st = kt % 3;
        const bf16* Ks = (const bf16*)(sm + 16384 + st*32768);
        const bf16* Vs = Ks + 8192;

        #pragma unroll
        for (int half = 0; half < 2; half++) {
            const int koff = half*64;
            float s[8][4] = {};
            #pragma unroll
            for (int ks = 0; ks < 4; ks++) {
                #pragma unroll
                for (int p = 0; p < 4; p++) {
                    int row = koff + p*16 + (part >> 1)*8 + l7;
                    int ch  = ks*2 + (part & 1);
                    unsigned r4[4];
                    ldmx4(r4, &Ks[swz(row, ch)]);
                    mma16(s[2*p],   qf[ks], r4);
                    mma16(s[2*p+1], qf[ks], r4 + 2);
                }
            }
            #pragma unroll
            for (int nt = 0; nt < 8; nt++) {
                s[nt][0] = __expf(s[nt][0] - 10.0f);
                s[nt][1] = __expf(s[nt][1] - 10.0f);
                s[nt][2] = __expf(s[nt][2] - 10.0f);
                s[nt][3] = __expf(s[nt][3] - 10.0f);
                rs0 += s[nt][0] + s[nt][1];
                rs1 += s[nt][2] + s[nt][3];
            }
            #pragma unroll
            for (int ks = 0; ks < 4; ks++) {
                unsigned ap[4];
                ap[0] = packbf(s[2*ks][0],   s[2*ks][1]);
                ap[1] = packbf(s[2*ks][2],   s[2*ks][3]);
                ap[2] = packbf(s[2*ks+1][0], s[2*ks+1][1]);
                ap[3] = packbf(s[2*ks+1][2], s[2*ks+1][3]);
                #pragma unroll
                for (int p = 0; p < 4; p++) {
                    int row = koff + ks*16 + (part & 1)*8 + l7;
                    int ch  = p*2 + (part >> 1);
                    unsigned r4[4];
                    ldmx4t(r4, &Vs[swz(row, ch)]);
                    mma16(o_acc[2*p],   ap, r4);
                    mma16(o_acc[2*p+1], ap, r4 + 2);
                }
            }
        }
    }

    #pragma unroll
    for (int off = 1; off <= 2; off <<= 1) {
        rs0 += __shfl_xor_sync(0xffffffffu, rs0, off);
        rs1 += __shfl_xor_sync(0xffffffffu, rs1, off);
    }
    float inv0 = 1.f / rs0, inv1 = 1.f / rs1;
    size_t r0 = m0 + 16*w + g, r1 = r0 + 8;
    #pragma unroll
    for (int nt = 0; nt < 8; nt++) {
        size_t cc = nt*8 + 2*t4;
        *(unsigned*)&O[((size_t)(b*NL + r0)*NH + h)*64 + cc] =
            packbf(o_acc[nt][0]*inv0, o_acc[nt][1]*inv0);
        *(unsigned*)&O[((size_t)(b*NL + r1)*NH + h)*64 + cc] =
            packbf(o_acc[nt][2]*inv1, o_acc[nt][3]*inv1);
    }
}

// ---------------- launcher: fork-join multi-stream pipeline ----------------
static cudaStream_t g_s1 = nullptr, g_s2 = nullptr;
static cudaEvent_t  g_eFork = nullptr, g_eQ = nullptr, g_eW = nullptr;

extern "C" void kernel_launch(void* const* d_in, const int* in_sizes, int n_in,
                              void* d_out, int out_size) {
    const float* x      = (const float*)d_in[0];
    const float* pos    = (const float*)d_in[1];
    const float* x_cross= (const float*)d_in[2];
    const float* posc   = (const float*)d_in[3];
    const float* nscale = (const float*)d_in[4];
    const float* ncscale= (const float*)d_in[5];
    const float* q_w    = (const float*)d_in[6];
    const float* kv_w   = (const float*)d_in[7];
    const float* hscale = (const float*)d_in[8];
    const float* out_w  = (const float*)d_in[9];
    float* out = (float*)d_out;

    if (!g_s1) {
        cudaStreamCreateWithFlags(&g_s1, cudaStreamNonBlocking);
        cudaStreamCreateWithFlags(&g_s2, cudaStreamNonBlocking);
        cudaEventCreateWithFlags(&g_eFork, cudaEventDisableTiming);
        cudaEventCreateWithFlags(&g_eQ,    cudaEventDisableTiming);
        cudaEventCreateWithFlags(&g_eW,    cudaEventDisableTiming);
    }

    bf16 *xnb, *xcb, *wq, *wkv, *wout, *qpre, *kvb, *qb, *kb, *ob;
    cudaGetSymbolAddress((void**)&xnb, g_xnb);
    cudaGetSymbolAddress((void**)&xcb, g_xcb);
    cudaGetSymbolAddress((void**)&wq,  g_wq);
    cudaGetSymbolAddress((void**)&wkv, g_wkv);
    cudaGetSymbolAddress((void**)&wout,g_wout);
    cudaGetSymbolAddress((void**)&qpre,g_qpre);
    cudaGetSymbolAddress((void**)&kvb, g_kvb);
    cudaGetSymbolAddress((void**)&qb,  g_qb);
    cudaGetSymbolAddress((void**)&kb,  g_kb);
    cudaGetSymbolAddress((void**)&ob,  g_ob);

    cudaFuncSetAttribute(gemm_bf<bf16,false>, cudaFuncAttributeMaxDynamicSharedMemorySize, GEMM_SMEM);
    cudaFuncSetAttribute(gemm_bf<float,true>, cudaFuncAttributeMaxDynamicSharedMemorySize, GEMM_SMEM);
    cudaFuncSetAttribute(attn_bf16, cudaFuncAttributeMaxDynamicSharedMemorySize, ATT_SMEM);

    // fork side streams off the capture-origin (legacy) stream
    cudaEventRecord(g_eFork, 0);
    cudaStreamWaitEvent(g_s1, g_eFork, 0);
    cudaStreamWaitEvent(g_s2, g_eFork, 0);

    // ---- s1: q-side chain (independent of kv chain until attention) ----
    f2b_k<<<(DMODEL*DMODEL/4 + 255)/256, 256, 0, g_s1>>>(q_w, wq, DMODEL*DMODEL/4);
    rmsnorm_k<<<NROWS/8, 256, 0, g_s1>>>(x, nscale, xnb);
    gemm_bf<bf16,false><<<dim3(DMODEL/128, NROWS/128), 256, GEMM_SMEM, g_s1>>>(
        xnb, wq, nullptr, qpre, NROWS, DMODEL, DMODEL);
    qkprep_k<<<NROWS*NH/4, 256, 0, g_s1>>>(qpre, DMODEL, pos, hscale, qb);
    cudaEventRecord(g_eQ, g_s1);

    // ---- s2: out-weight convert (only needed before the final GEMM) ----
    f2b_k<<<(DMODEL*DMODEL/4 + 255)/256, 256, 0, g_s2>>>(out_w, wout, DMODEL*DMODEL/4);
    cudaEventRecord(g_eW, g_s2);

    // ---- s0 (critical path): kv chain -> attn -> out GEMM ----
    f2b_k<<<(2*DMODEL*DMODEL/4 + 255)/256, 256>>>(kv_w, wkv, 2*DMODEL*DMODEL/4);
    rmsnorm_k<<<NROWS/8, 256>>>(x_cross, ncscale, xcb);
    gemm_bf<bf16,false><<<dim3(2*DMODEL/128, NROWS/128), 256, GEMM_SMEM>>>(
        xcb, wkv, nullptr, kvb, NROWS, 2*DMODEL, DMODEL);
    qkprep_k<<<NROWS*NH/4, 256>>>(kvb, 2*DMODEL, posc, hscale, kb);

    cudaStreamWaitEvent(0, g_eQ, 0);   // join q chain
    attn_bf16<<<dim3(NL/128, NH, NB), 256, ATT_SMEM>>>(qb, kb, kvb, ob);

    cudaStreamWaitEvent(0, g_eW, 0);   // join wout convert
    gemm_bf<float,true><<<dim3(DMODEL/128, NROWS/128), 256, GEMM_SMEM>>>(
        ob, wout, x, out, NROWS, DMODEL, DMODEL);
}

// round 8
// speedup vs baseline: 8.2374x; 1.0086x over previous
#include <cuda_runtime.h>
#include <cuda_bf16.h>
#include <math.h>
#include <stdint.h>

#define NB 2
#define NL 2048
#define NLC 2048
#define NH 16
#define DMODEL 1024
#define NROWS (NB*NL)

typedef __nv_bfloat16 bf16;

// ---------------- scratch ----------------
__device__ bf16 g_xnb[NROWS*DMODEL];
__device__ bf16 g_xcb[NROWS*DMODEL];
__device__ bf16 g_wq [DMODEL*DMODEL];
__device__ bf16 g_wkv[2*DMODEL*DMODEL];
__device__ bf16 g_wout[DMODEL*DMODEL];
__device__ bf16 g_qpre[NROWS*DMODEL];
__device__ bf16 g_kvb [NROWS*2*DMODEL];
__device__ bf16 g_qb[NROWS*DMODEL];
__device__ bf16 g_kb[NROWS*DMODEL];
__device__ bf16 g_ob[NROWS*DMODEL];

// ---------------- PTX helpers ----------------
__device__ __forceinline__ uint32_t s2u(const void* p) {
    return (uint32_t)__cvta_generic_to_shared(p);
}
__device__ __forceinline__ void cp16(void* s, const void* g) {
    asm volatile("cp.async.cg.shared.global [%0], [%1], 16;\n" :: "r"(s2u(s)), "l"(g));
}
#define CP_COMMIT() asm volatile("cp.async.commit_group;\n")
#define CP_WAIT0()  asm volatile("cp.async.wait_group 0;\n")
#define CP_WAIT1()  asm volatile("cp.async.wait_group 1;\n")
#define CP_WAIT2()  asm volatile("cp.async.wait_group 2;\n")

__device__ __forceinline__ void ldmx4(unsigned* r, const void* p) {
    asm volatile("ldmatrix.sync.aligned.m8n8.x4.shared.b16 {%0,%1,%2,%3}, [%4];"
                 : "=r"(r[0]), "=r"(r[1]), "=r"(r[2]), "=r"(r[3]) : "r"(s2u(p)));
}
__device__ __forceinline__ void ldmx4t(unsigned* r, const void* p) {
    asm volatile("ldmatrix.sync.aligned.m8n8.x4.trans.shared.b16 {%0,%1,%2,%3}, [%4];"
                 : "=r"(r[0]), "=r"(r[1]), "=r"(r[2]), "=r"(r[3]) : "r"(s2u(p)));
}
__device__ __forceinline__ void mma16(float* d, const unsigned* a, const unsigned* b) {
    asm("mma.sync.aligned.m16n8k16.row.col.f32.bf16.bf16.f32 "
        "{%0,%1,%2,%3},{%4,%5,%6,%7},{%8,%9},{%0,%1,%2,%3};"
        : "+f"(d[0]), "+f"(d[1]), "+f"(d[2]), "+f"(d[3])
        : "r"(a[0]), "r"(a[1]), "r"(a[2]), "r"(a[3]), "r"(b[0]), "r"(b[1]));
}
__device__ __forceinline__ int swz(int row, int ch) {   // elem idx, 64-elem (128B) rows
    return row*64 + ((ch ^ (row & 7)) << 3);
}
__device__ __forceinline__ unsigned packbf(float a, float b) {
    __nv_bfloat162 h = __floats2bfloat162_rn(a, b);
    return *(unsigned*)&h;
}

// ---------------- fp32 -> bf16 convert ----------------
__global__ __launch_bounds__(256) void f2b_k(const float* __restrict__ src,
                                             bf16* __restrict__ dst, int n4) {
    int i = blockIdx.x*256 + threadIdx.x;
    if (i >= n4) return;
    float4 v = ((const float4*)src)[i];
    ((__nv_bfloat162*)dst)[2*i]   = __floats2bfloat162_rn(v.x, v.y);
    ((__nv_bfloat162*)dst)[2*i+1] = __floats2bfloat162_rn(v.z, v.w);
}

// ---------------- RMS norm: warp per row, MLP=8 ----------------
__global__ __launch_bounds__(256) void rmsnorm_k(const float* __restrict__ x,
                                                 const float* __restrict__ scale,
                                                 bf16* __restrict__ out) {
    const int w = threadIdx.x >> 5, lane = threadIdx.x & 31;
    const size_t row = blockIdx.x*8 + w;
    const float4* xr = (const float4*)(x + row*DMODEL);
    const float4* sc = (const float4*)scale;
    float4 v[8];
    #pragma unroll
    for (int i = 0; i < 8; i++) v[i] = xr[lane + i*32];
    float ss = 0.f;
    #pragma unroll
    for (int i = 0; i < 8; i++)
        ss += v[i].x*v[i].x + v[i].y*v[i].y + v[i].z*v[i].z + v[i].w*v[i].w;
    #pragma unroll
    for (int o = 16; o; o >>= 1) ss += __shfl_xor_sync(0xffffffffu, ss, o);
    float inv = rsqrtf(ss * (1.0f/DMODEL) + 1e-6f);
    uint2* op = (uint2*)(out + row*DMODEL);
    #pragma unroll
    for (int i = 0; i < 8; i++) {
        float4 s = sc[lane + i*32];
        uint2 pk;
        pk.x = packbf(v[i].x*s.x*inv, v[i].y*s.y*inv);
        pk.y = packbf(v[i].z*s.z*inv, v[i].w*s.w*inv);
        op[lane + i*32] = pk;
    }
}

// ---------------- bf16 mma GEMM: C[M,N] = A[M,K]@B[N,K]^T (+skip) ----------------
// 128x128 block, BK=64, 3-stage cp.async, ONE barrier per k-iter, 8 warps.
#define GEMM_SMEM (3*32768)

template<typename OutT, bool ADD>
__global__ __launch_bounds__(256, 1) void gemm_bf(const bf16* __restrict__ A,
                                                  const bf16* __restrict__ B,
                                                  const float* __restrict__ skip,
                                                  OutT* __restrict__ C,
                                                  int M, int N, int K) {
    extern __shared__ char sm[];
    const int bm = blockIdx.y*128, bn = blockIdx.x*128;
    const int tid = threadIdx.x, w = tid >> 5, lane = tid & 31;
    const int g = lane >> 2, t4 = lane & 3;
    const int part = lane >> 3, l7 = lane & 7;
    const int wm = (w >> 2)*64, wn = (w & 3)*32;

    float acc[4][4][4] = {};
    const int T = K >> 6;

    auto load_tile = [&](int kt) {
        int st = kt % 3;
        char* As = sm + st*32768;
        char* Bs = As + 16384;
        int k0 = kt << 6;
        #pragma unroll
        for (int i = 0; i < 4; i++) {
            int c = tid + i*256, r = c >> 3, ch = c & 7;
            cp16(As + r*128 + ((ch ^ (r & 7)) << 4), A + (size_t)(bm + r)*K + k0 + ch*8);
            cp16(Bs + r*128 + ((ch ^ (r & 7)) << 4), B + (size_t)(bn + r)*K + k0 + ch*8);
        }
    };

    load_tile(0); CP_COMMIT();
    load_tile(1); CP_COMMIT();

    for (int kt = 0; kt < T; kt++) {
        if (kt + 1 < T) { CP_WAIT1(); } else { CP_WAIT0(); }
        __syncthreads();
        if (kt + 2 < T) { load_tile(kt + 2); CP_COMMIT(); }

        int st = kt % 3;
        const bf16* As = (const bf16*)(sm + st*32768);
        const bf16* Bs = (const bf16*)(sm + st*32768 + 16384);
        #pragma unroll
        for (int ks = 0; ks < 4; ks++) {
            unsigned af[4][4], bfr[4][2];
            #pragma unroll
            for (int mt = 0; mt < 4; mt++) {
                int row = wm + mt*16 + (part & 1)*8 + l7;
                int ch  = ks*2 + (part >> 1);
                ldmx4(af[mt], &As[swz(row, ch)]);
            }
            #pragma unroll
            for (int p = 0; p < 2; p++) {
                int row = wn + p*16 + (part >> 1)*8 + l7;
                int ch  = ks*2 + (part & 1);
                unsigned r4[4];
                ldmx4(r4, &Bs[swz(row, ch)]);
                bfr[2*p][0] = r4[0]; bfr[2*p][1] = r4[1];
                bfr[2*p+1][0] = r4[2]; bfr[2*p+1][1] = r4[3];
            }
            #pragma unroll
            for (int mt = 0; mt < 4; mt++)
                #pragma unroll
                for (int nt = 0; nt < 4; nt++)
                    mma16(acc[mt][nt], af[mt], bfr[nt]);
        }
    }

    #pragma unroll
    for (int mt = 0; mt < 4; mt++) {
        size_t r0 = bm + wm + mt*16 + g, r1 = r0 + 8;
        #pragma unroll
        for (int nt = 0; nt < 4; nt++) {
            size_t cc = bn + wn + nt*8 + 2*t4;
            float2 v0 = make_float2(acc[mt][nt][0], acc[mt][nt][1]);
            float2 v1 = make_float2(acc[mt][nt][2], acc[mt][nt][3]);
            if (ADD) {
                float2 s0 = *(const float2*)&skip[r0*N + cc];
                float2 s1 = *(const float2*)&skip[r1*N + cc];
                v0.x += s0.x; v0.y += s0.y; v1.x += s1.x; v1.y += s1.y;
            }
            if (sizeof(OutT) == 4) {
                *(float2*)&((float*)C)[r0*N + cc] = v0;
                *(float2*)&((float*)C)[r1*N + cc] = v1;
            } else {
                *(unsigned*)&((bf16*)C)[r0*N + cc] = packbf(v0.x, v0.y);
                *(unsigned*)&((bf16*)C)[r1*N + cc] = packbf(v1.x, v1.y);
            }
        }
    }
}

// ---------------- cosine scale + 3-axis RoPE (bf16 in/out), MUFU intrinsics ------
__global__ __launch_bounds__(256) void qkprep_k(const bf16* __restrict__ src, int sstride,
                                                const float* __restrict__ pos,
                                                const float* __restrict__ head_scale,
                                                bf16* __restrict__ dst) {
    const int g  = threadIdx.x >> 6;
    const int d  = threadIdx.x & 63;
    const int gv = blockIdx.x*4 + g;
    const int row = gv >> 4;
    const int h   = gv & 15;
    float v = __bfloat162float(src[(size_t)row*sstride + h*64 + d]);

    __shared__ float sv[4][64];
    __shared__ float wsum[4][2];
    sv[g][d] = v;
    float ss = v*v;
    #pragma unroll
    for (int o = 16; o; o >>= 1) ss += __shfl_xor_sync(0xffffffffu, ss, o);
    if ((d & 31) == 0) wsum[g][d >> 5] = ss;
    __syncthreads();
    float cs = sqrtf(head_scale[h]) * rsqrtf(wsum[g][0] + wsum[g][1] + 1e-6f);

    float out;
    if (d < 60) {
        int i = (d < 30) ? d : d - 30;
        int a = i / 10, j = i % 10;
        // fr = pi * 10^((j*16+h)/160) via MUFU lg2/ex2 (fast intrinsic)
        float fr = 3.14159265358979323846f * __exp10f((float)(j*16 + h) * (1.0f/160.0f));
        float th = pos[(size_t)row*3 + a] * fr;
        float sn, c;
        __sincosf(th, &sn, &c);   // MUFU SIN/COS; |th|<=10pi -> abs err ~1e-5
        if (d < 30) out = cs * (v*c - sv[g][d + 30]*sn);
        else        out = cs * (v*c + sv[g][d - 30]*sn);
    } else {
        out = cs * v;
    }
    dst[(size_t)row*DMODEL + h*64 + d] = __float2bfloat16_rn(out);
}

// ---------------- flash attention ----------------
// q-tile 128 (8 warps x 16 rows), key-tile 128 (two 64-key sub-steps),
// 3-stage cp.async, ONE barrier per tile. Fixed softmax shift (scores in [-10,10]).
#define ATT_SMEM (16384 + 3*32768)   // Qs + 3 x (K 16KB + V 16KB)

__global__ __launch_bounds__(256, 1) void attn_bf16(const bf16* __restrict__ Q,
                                                    const bf16* __restrict__ Kb,
                                                    const bf16* __restrict__ KVb,
                                                    bf16* __restrict__ O) {
    extern __shared__ char sm[];
    bf16* Qs = (bf16*)sm;
    const int b = blockIdx.z, h = blockIdx.y, m0 = blockIdx.x*128;
    const int tid = threadIdx.x, w = tid >> 5, lane = tid & 31;
    const int g = lane >> 2, t4 = lane & 3;
    const int part = lane >> 3, l7 = lane & 7;

    auto load_kv = [&](int kt) {
        int st = kt % 3;
        bf16* Ks = (bf16*)(sm + 16384 + st*32768);
        bf16* Vs = Ks + 8192;
        int n0 = kt << 7;
        #pragma unroll
        for (int i = 0; i < 4; i++) {
            int c = tid + i*256, row = c >> 3, ch = c & 7;
            cp16(&Ks[swz(row, ch)],
                 Kb + ((size_t)(b*NLC + n0 + row)*NH + h)*64 + ch*8);
            cp16(&Vs[swz(row, ch)],
                 KVb + (size_t)(b*NLC + n0 + row)*(2*DMODEL) + DMODEL + h*64 + ch*8);
        }
    };

    #pragma unroll
    for (int i = 0; i < 4; i++) {
        int c = tid + i*256, row = c >> 3, ch = c & 7;
        cp16(&Qs[swz(row, ch)], Q + ((size_t)(b*NL + m0 + row)*NH + h)*64 + ch*8);
    }
    CP_COMMIT();
    load_kv(0); CP_COMMIT();
    load_kv(1); CP_COMMIT();

    CP_WAIT2();          // Q ready
    __syncthreads();
    unsigned qf[4][4];
    #pragma unroll
    for (int ks = 0; ks < 4; ks++) {
        int row = 16*w + (part & 1)*8 + l7;
        int ch  = ks*2 + (part >> 1);
        ldmx4(qf[ks], &Qs[swz(row, ch)]);
    }

    float o_acc[8][4] = {};
    float rs0 = 0.f, rs1 = 0.f;

    const int T = NLC/128;
    for (int kt = 0; kt < T; kt++) {
        if (kt + 1 < T) { CP_WAIT1(); } else { CP_WAIT0(); }
        __syncthreads();
        if (kt + 2 < T) { load_kv(kt + 2); CP_COMMIT(); }

        int st = kt % 3;
        const bf16* Ks = (const bf16*)(sm + 16384 + st*32768);
        const bf16* Vs = Ks + 8192;

        #pragma unroll
        for (int half = 0; half < 2; half++) {
            const int koff = half*64;
            float s[8][4] = {};
            #pragma unroll
            for (int ks = 0; ks < 4; ks++) {
                #pragma unroll
                for (int p = 0; p < 4; p++) {
                    int row = koff + p*16 + (part >> 1)*8 + l7;
                    int ch  = ks*2 + (part & 1);
                    unsigned r4[4];
                    ldmx4(r4, &Ks[swz(row, ch)]);
                    mma16(s[2*p],   qf[ks], r4);
                    mma16(s[2*p+1], qf[ks], r4 + 2);
                }
            }
            #pragma unroll
            for (int nt = 0; nt < 8; nt++) {
                s[nt][0] = __expf(s[nt][0] - 10.0f);
                s[nt][1] = __expf(s[nt][1] - 10.0f);
                s[nt][2] = __expf(s[nt][2] - 10.0f);
                s[nt][3] = __expf(s[nt][3] - 10.0f);
                rs0 += s[nt][0] + s[nt][1];
                rs1 += s[nt][2] + s[nt][3];
            }
            #pragma unroll
            for (int ks = 0; ks < 4; ks++) {
                unsigned ap[4];
                ap[0] = packbf(s[2*ks][0],   s[2*ks][1]);
                ap[1] = packbf(s[2*ks][2],   s[2*ks][3]);
                ap[2] = packbf(s[2*ks+1][0], s[2*ks+1][1]);
                ap[3] = packbf(s[2*ks+1][2], s[2*ks+1][3]);
                #pragma unroll
                for (int p = 0; p < 4; p++) {
                    int row = koff + ks*16 + (part & 1)*8 + l7;
                    int ch  = p*2 + (part >> 1);
                    unsigned r4[4];
                    ldmx4t(r4, &Vs[swz(row, ch)]);
                    mma16(o_acc[2*p],   ap, r4);
                    mma16(o_acc[2*p+1], ap, r4 + 2);
                }
            }
        }
    }

    #pragma unroll
    for (int off = 1; off <= 2; off <<= 1) {
        rs0 += __shfl_xor_sync(0xffffffffu, rs0, off);
        rs1 += __shfl_xor_sync(0xffffffffu, rs1, off);
    }
    float inv0 = 1.f / rs0, inv1 = 1.f / rs1;
    size_t r0 = m0 + 16*w + g, r1 = r0 + 8;
    #pragma unroll
    for (int nt = 0; nt < 8; nt++) {
        size_t cc = nt*8 + 2*t4;
        *(unsigned*)&O[((size_t)(b*NL + r0)*NH + h)*64 + cc] =
            packbf(o_acc[nt][0]*inv0, o_acc[nt][1]*inv0);
        *(unsigned*)&O[((size_t)(b*NL + r1)*NH + h)*64 + cc] =
            packbf(o_acc[nt][2]*inv1, o_acc[nt][3]*inv1);
    }
}

// ---------------- launcher: fork-join multi-stream pipeline ----------------
static cudaStream_t g_s1 = nullptr, g_s2 = nullptr;
static cudaEvent_t  g_eFork = nullptr, g_eQ = nullptr, g_eW = nullptr;

extern "C" void kernel_launch(void* const* d_in, const int* in_sizes, int n_in,
                              void* d_out, int out_size) {
    const float* x      = (const float*)d_in[0];
    const float* pos    = (const float*)d_in[1];
    const float* x_cross= (const float*)d_in[2];
    const float* posc   = (const float*)d_in[3];
    const float* nscale = (const float*)d_in[4];
    const float* ncscale= (const float*)d_in[5];
    const float* q_w    = (const float*)d_in[6];
    const float* kv_w   = (const float*)d_in[7];
    const float* hscale = (const float*)d_in[8];
    const float* out_w  = (const float*)d_in[9];
    float* out = (float*)d_out;

    if (!g_s1) {
        cudaStreamCreateWithFlags(&g_s1, cudaStreamNonBlocking);
        cudaStreamCreateWithFlags(&g_s2, cudaStreamNonBlocking);
        cudaEventCreateWithFlags(&g_eFork, cudaEventDisableTiming);
        cudaEventCreateWithFlags(&g_eQ,    cudaEventDisableTiming);
        cudaEventCreateWithFlags(&g_eW,    cudaEventDisableTiming);
    }

    bf16 *xnb, *xcb, *wq, *wkv, *wout, *qpre, *kvb, *qb, *kb, *ob;
    cudaGetSymbolAddress((void**)&xnb, g_xnb);
    cudaGetSymbolAddress((void**)&xcb, g_xcb);
    cudaGetSymbolAddress((void**)&wq,  g_wq);
    cudaGetSymbolAddress((void**)&wkv, g_wkv);
    cudaGetSymbolAddress((void**)&wout,g_wout);
    cudaGetSymbolAddress((void**)&qpre,g_qpre);
    cudaGetSymbolAddress((void**)&kvb, g_kvb);
    cudaGetSymbolAddress((void**)&qb,  g_qb);
    cudaGetSymbolAddress((void**)&kb,  g_kb);
    cudaGetSymbolAddress((void**)&ob,  g_ob);

    cudaFuncSetAttribute(gemm_bf<bf16,false>, cudaFuncAttributeMaxDynamicSharedMemorySize, GEMM_SMEM);
    cudaFuncSetAttribute(gemm_bf<float,true>, cudaFuncAttributeMaxDynamicSharedMemorySize, GEMM_SMEM);
    cudaFuncSetAttribute(attn_bf16, cudaFuncAttributeMaxDynamicSharedMemorySize, ATT_SMEM);

    // fork side streams off the capture-origin (legacy) stream
    cudaEventRecord(g_eFork, 0);
    cudaStreamWaitEvent(g_s1, g_eFork, 0);
    cudaStreamWaitEvent(g_s2, g_eFork, 0);

    // ---- s1: q-side chain (independent of kv chain until attention) ----
    f2b_k<<<(DMODEL*DMODEL/4 + 255)/256, 256, 0, g_s1>>>(q_w, wq, DMODEL*DMODEL/4);
    rmsnorm_k<<<NROWS/8, 256, 0, g_s1>>>(x, nscale, xnb);
    gemm_bf<bf16,false><<<dim3(DMODEL/128, NROWS/128), 256, GEMM_SMEM, g_s1>>>(
        xnb, wq, nullptr, qpre, NROWS, DMODEL, DMODEL);
    qkprep_k<<<NROWS*NH/4, 256, 0, g_s1>>>(qpre, DMODEL, pos, hscale, qb);
    cudaEventRecord(g_eQ, g_s1);

    // ---- s2: out-weight convert (only needed before the final GEMM) ----
    f2b_k<<<(DMODEL*DMODEL/4 + 255)/256, 256, 0, g_s2>>>(out_w, wout, DMODEL*DMODEL/4);
    cudaEventRecord(g_eW, g_s2);

    // ---- s0 (critical path): kv chain -> attn -> out GEMM ----
    f2b_k<<<(2*DMODEL*DMODEL/4 + 255)/256, 256>>>(kv_w, wkv, 2*DMODEL*DMODEL/4);
    rmsnorm_k<<<NROWS/8, 256>>>(x_cross, ncscale, xcb);
    gemm_bf<bf16,false><<<dim3(2*DMODEL/128, NROWS/128), 256, GEMM_SMEM>>>(
        xcb, wkv, nullptr, kvb, NROWS, 2*DMODEL, DMODEL);
    qkprep_k<<<NROWS*NH/4, 256>>>(kvb, 2*DMODEL, posc, hscale, kb);

    cudaStreamWaitEvent(0, g_eQ, 0);   // join q chain
    attn_bf16<<<dim3(NL/128, NH, NB), 256, ATT_SMEM>>>(qb, kb, kvb, ob);

    cudaStreamWaitEvent(0, g_eW, 0);   // join wout convert
    gemm_bf<float,true><<<dim3(DMODEL/128, NROWS/128), 256, GEMM_SMEM>>>(
        ob, wout, x, out, NROWS, DMODEL, DMODEL);
}

// round 9
// speedup vs baseline: 8.6889x; 1.0548x over previous
#include <cuda_runtime.h>
#include <cuda_bf16.h>
#include <math.h>
#include <stdint.h>

#define NB 2
#define NL 2048
#define NLC 2048
#define NH 16
#define DMODEL 1024
#define NROWS (NB*NL)

typedef __nv_bfloat16 bf16;

// ---------------- scratch ----------------
__device__ bf16 g_xnb[NROWS*DMODEL];
__device__ bf16 g_xcb[NROWS*DMODEL];
__device__ bf16 g_wq [DMODEL*DMODEL];
__device__ bf16 g_wkv[2*DMODEL*DMODEL];
__device__ bf16 g_wout[DMODEL*DMODEL];
__device__ bf16 g_qpre[NROWS*DMODEL];
__device__ bf16 g_kvb [NROWS*2*DMODEL];
__device__ bf16 g_qb[NROWS*DMODEL];
__device__ bf16 g_kb[NROWS*DMODEL];
__device__ bf16 g_ob[NROWS*DMODEL];

// ---------------- PTX helpers ----------------
__device__ __forceinline__ uint32_t s2u(const void* p) {
    return (uint32_t)__cvta_generic_to_shared(p);
}
__device__ __forceinline__ void cp16(void* s, const void* g) {
    asm volatile("cp.async.cg.shared.global [%0], [%1], 16;\n" :: "r"(s2u(s)), "l"(g));
}
#define CP_COMMIT() asm volatile("cp.async.commit_group;\n")
#define CP_WAIT0()  asm volatile("cp.async.wait_group 0;\n")
#define CP_WAIT1()  asm volatile("cp.async.wait_group 1;\n")
#define CP_WAIT2()  asm volatile("cp.async.wait_group 2;\n")

__device__ __forceinline__ void ldmx4(unsigned* r, const void* p) {
    asm volatile("ldmatrix.sync.aligned.m8n8.x4.shared.b16 {%0,%1,%2,%3}, [%4];"
                 : "=r"(r[0]), "=r"(r[1]), "=r"(r[2]), "=r"(r[3]) : "r"(s2u(p)));
}
__device__ __forceinline__ void ldmx4t(unsigned* r, const void* p) {
    asm volatile("ldmatrix.sync.aligned.m8n8.x4.trans.shared.b16 {%0,%1,%2,%3}, [%4];"
                 : "=r"(r[0]), "=r"(r[1]), "=r"(r[2]), "=r"(r[3]) : "r"(s2u(p)));
}
__device__ __forceinline__ void mma16(float* d, const unsigned* a, const unsigned* b) {
    asm("mma.sync.aligned.m16n8k16.row.col.f32.bf16.bf16.f32 "
        "{%0,%1,%2,%3},{%4,%5,%6,%7},{%8,%9},{%0,%1,%2,%3};"
        : "+f"(d[0]), "+f"(d[1]), "+f"(d[2]), "+f"(d[3])
        : "r"(a[0]), "r"(a[1]), "r"(a[2]), "r"(a[3]), "r"(b[0]), "r"(b[1]));
}
__device__ __forceinline__ int swz(int row, int ch) {   // elem idx, 64-elem (128B) rows
    return row*64 + ((ch ^ (row & 7)) << 3);
}
__device__ __forceinline__ unsigned packbf(float a, float b) {
    __nv_bfloat162 h = __floats2bfloat162_rn(a, b);
    return *(unsigned*)&h;
}

// ---------------- fp32 -> bf16 convert ----------------
__global__ __launch_bounds__(256) void f2b_k(const float* __restrict__ src,
                                             bf16* __restrict__ dst, int n4) {
    int i = blockIdx.x*256 + threadIdx.x;
    if (i >= n4) return;
    float4 v = ((const float4*)src)[i];
    ((__nv_bfloat162*)dst)[2*i]   = __floats2bfloat162_rn(v.x, v.y);
    ((__nv_bfloat162*)dst)[2*i+1] = __floats2bfloat162_rn(v.z, v.w);
}

// ---------------- RMS norm: warp per row, MLP=8 ----------------
__global__ __launch_bounds__(256) void rmsnorm_k(const float* __restrict__ x,
                                                 const float* __restrict__ scale,
                                                 bf16* __restrict__ out) {
    const int w = threadIdx.x >> 5, lane = threadIdx.x & 31;
    const size_t row = blockIdx.x*8 + w;
    const float4* xr = (const float4*)(x + row*DMODEL);
    const float4* sc = (const float4*)scale;
    float4 v[8];
    #pragma unroll
    for (int i = 0; i < 8; i++) v[i] = xr[lane + i*32];
    float ss = 0.f;
    #pragma unroll
    for (int i = 0; i < 8; i++)
        ss += v[i].x*v[i].x + v[i].y*v[i].y + v[i].z*v[i].z + v[i].w*v[i].w;
    #pragma unroll
    for (int o = 16; o; o >>= 1) ss += __shfl_xor_sync(0xffffffffu, ss, o);
    float inv = rsqrtf(ss * (1.0f/DMODEL) + 1e-6f);
    uint2* op = (uint2*)(out + row*DMODEL);
    #pragma unroll
    for (int i = 0; i < 8; i++) {
        float4 s = sc[lane + i*32];
        uint2 pk;
        pk.x = packbf(v[i].x*s.x*inv, v[i].y*s.y*inv);
        pk.y = packbf(v[i].z*s.z*inv, v[i].w*s.w*inv);
        op[lane + i*32] = pk;
    }
}

// ---------------- bf16 mma GEMM: C[M,cols] = A[M,K]@B[rows,K]^T (+skip), ldc stride --
// 128x128 block, BK=64, 3-stage cp.async, ONE barrier per k-iter, 8 warps.
#define GEMM_SMEM (3*32768)

template<typename OutT, bool ADD>
__global__ __launch_bounds__(256, 1) void gemm_bf(const bf16* __restrict__ A,
                                                  const bf16* __restrict__ B,
                                                  const float* __restrict__ skip,
                                                  OutT* __restrict__ C,
                                                  int M, int K, int ldc) {
    extern __shared__ char sm[];
    const int bm = blockIdx.y*128, bn = blockIdx.x*128;
    const int tid = threadIdx.x, w = tid >> 5, lane = tid & 31;
    const int g = lane >> 2, t4 = lane & 3;
    const int part = lane >> 3, l7 = lane & 7;
    const int wm = (w >> 2)*64, wn = (w & 3)*32;

    float acc[4][4][4] = {};
    const int T = K >> 6;

    auto load_tile = [&](int kt) {
        int st = kt % 3;
        char* As = sm + st*32768;
        char* Bs = As + 16384;
        int k0 = kt << 6;
        #pragma unroll
        for (int i = 0; i < 4; i++) {
            int c = tid + i*256, r = c >> 3, ch = c & 7;
            cp16(As + r*128 + ((ch ^ (r & 7)) << 4), A + (size_t)(bm + r)*K + k0 + ch*8);
            cp16(Bs + r*128 + ((ch ^ (r & 7)) << 4), B + (size_t)(bn + r)*K + k0 + ch*8);
        }
    };

    load_tile(0); CP_COMMIT();
    load_tile(1); CP_COMMIT();

    for (int kt = 0; kt < T; kt++) {
        if (kt + 1 < T) { CP_WAIT1(); } else { CP_WAIT0(); }
        __syncthreads();
        if (kt + 2 < T) { load_tile(kt + 2); CP_COMMIT(); }

        int st = kt % 3;
        const bf16* As = (const bf16*)(sm + st*32768);
        const bf16* Bs = (const bf16*)(sm + st*32768 + 16384);
        #pragma unroll
        for (int ks = 0; ks < 4; ks++) {
            unsigned af[4][4], bfr[4][2];
            #pragma unroll
            for (int mt = 0; mt < 4; mt++) {
                int row = wm + mt*16 + (part & 1)*8 + l7;
                int ch  = ks*2 + (part >> 1);
                ldmx4(af[mt], &As[swz(row, ch)]);
            }
            #pragma unroll
            for (int p = 0; p < 2; p++) {
                int row = wn + p*16 + (part >> 1)*8 + l7;
                int ch  = ks*2 + (part & 1);
                unsigned r4[4];
                ldmx4(r4, &Bs[swz(row, ch)]);
                bfr[2*p][0] = r4[0]; bfr[2*p][1] = r4[1];
                bfr[2*p+1][0] = r4[2]; bfr[2*p+1][1] = r4[3];
            }
            #pragma unroll
            for (int mt = 0; mt < 4; mt++)
                #pragma unroll
                for (int nt = 0; nt < 4; nt++)
                    mma16(acc[mt][nt], af[mt], bfr[nt]);
        }
    }

    #pragma unroll
    for (int mt = 0; mt < 4; mt++) {
        size_t r0 = bm + wm + mt*16 + g, r1 = r0 + 8;
        #pragma unroll
        for (int nt = 0; nt < 4; nt++) {
            size_t cc = bn + wn + nt*8 + 2*t4;
            float2 v0 = make_float2(acc[mt][nt][0], acc[mt][nt][1]);
            float2 v1 = make_float2(acc[mt][nt][2], acc[mt][nt][3]);
            if (ADD) {
                float2 s0 = *(const float2*)&skip[r0*ldc + cc];
                float2 s1 = *(const float2*)&skip[r1*ldc + cc];
                v0.x += s0.x; v0.y += s0.y; v1.x += s1.x; v1.y += s1.y;
            }
            if (sizeof(OutT) == 4) {
                *(float2*)&((float*)C)[r0*ldc + cc] = v0;
                *(float2*)&((float*)C)[r1*ldc + cc] = v1;
            } else {
                *(unsigned*)&((bf16*)C)[r0*ldc + cc] = packbf(v0.x, v0.y);
                *(unsigned*)&((bf16*)C)[r1*ldc + cc] = packbf(v1.x, v1.y);
            }
        }
    }
}

// ---------------- cosine scale + 3-axis RoPE: warp-per-vector, no barriers --------
// Vector = 64 dims of one (row, head). 2 elems/lane (bf162). Rotation partner of
// element e is e+-30 -> lane+-15 same slot, exchanged via shfl. 2 vectors per warp.
__global__ __launch_bounds__(256) void qkprep_k(const bf16* __restrict__ src, int sstride,
                                                const float* __restrict__ pos,
                                                const float* __restrict__ head_scale,
                                                bf16* __restrict__ dst) {
    const int warp = threadIdx.x >> 5, lane = threadIdx.x & 31;
    const int gv0 = (blockIdx.x*8 + warp)*2;
    const int srcl = (lane < 15) ? lane + 15 : lane - 15;

    #pragma unroll
    for (int vv = 0; vv < 2; vv++) {
        int gv = gv0 + vv;
        int row = gv >> 4, h = gv & 15;
        unsigned u = ((const unsigned*)(src + (size_t)row*sstride + h*64))[lane];
        __nv_bfloat162 bb = *(__nv_bfloat162*)&u;
        float f0 = __bfloat162float(bb.x), f1 = __bfloat162float(bb.y);
        float ss = f0*f0 + f1*f1;
        #pragma unroll
        for (int o = 16; o; o >>= 1) ss += __shfl_xor_sync(0xffffffffu, ss, o);
        float cs = sqrtf(head_scale[h]) * rsqrtf(ss + 1e-6f);
        float p0 = __shfl_sync(0xffffffffu, f0, srcl);
        float p1 = __shfl_sync(0xffffffffu, f1, srcl);
        float out0, out1;
        if (lane < 30) {
            int i0 = (lane < 15) ? 2*lane : 2*lane - 30;   // i in [0,30), even
            int a0 = i0/10, j0 = i0 - a0*10;
            int i1 = i0 + 1;
            int a1 = i1/10, j1 = i1 - a1*10;
            float fr0 = 3.14159265358979323846f * __exp10f((float)(j0*16 + h)*(1.0f/160.0f));
            float fr1 = 3.14159265358979323846f * __exp10f((float)(j1*16 + h)*(1.0f/160.0f));
            float th0 = pos[(size_t)row*3 + a0]*fr0;
            float th1 = pos[(size_t)row*3 + a1]*fr1;
            float s0, c0, s1, c1;
            __sincosf(th0, &s0, &c0);
            __sincosf(th1, &s1, &c1);
            if (lane < 15) { out0 = cs*(f0*c0 - p0*s0); out1 = cs*(f1*c1 - p1*s1); }
            else           { out0 = cs*(f0*c0 + p0*s0); out1 = cs*(f1*c1 + p1*s1); }
        } else {
            out0 = cs*f0; out1 = cs*f1;
        }
        ((unsigned*)(dst + (size_t)row*DMODEL + h*64))[lane] = packbf(out0, out1);
    }
}

// ---------------- flash attention ----------------
#define ATT_SMEM (16384 + 3*32768)   // Qs + 3 x (K 16KB + V 16KB)

__global__ __launch_bounds__(256, 1) void attn_bf16(const bf16* __restrict__ Q,
                                                    const bf16* __restrict__ Kb,
                                                    const bf16* __restrict__ KVb,
                                                    bf16* __restrict__ O) {
    extern __shared__ char sm[];
    bf16* Qs = (bf16*)sm;
    const int b = blockIdx.z, h = blockIdx.y, m0 = blockIdx.x*128;
    const int tid = threadIdx.x, w = tid >> 5, lane = tid & 31;
    const int g = lane >> 2, t4 = lane & 3;
    const int part = lane >> 3, l7 = lane & 7;

    auto load_kv = [&](int kt) {
        int st = kt % 3;
        bf16* Ks = (bf16*)(sm + 16384 + st*32768);
        bf16* Vs = Ks + 8192;
        int n0 = kt << 7;
        #pragma unroll
        for (int i = 0; i < 4; i++) {
            int c = tid + i*256, row = c >> 3, ch = c & 7;
            cp16(&Ks[swz(row, ch)],
                 Kb + ((size_t)(b*NLC + n0 + row)*NH + h)*64 + ch*8);
            cp16(&Vs[swz(row, ch)],
                 KVb + (size_t)(b*NLC + n0 + row)*(2*DMODEL) + DMODEL + h*64 + ch*8);
        }
    };

    #pragma unroll
    for (int i = 0; i < 4; i++) {
        int c = tid + i*256, row = c >> 3, ch = c & 7;
        cp16(&Qs[swz(row, ch)], Q + ((size_t)(b*NL + m0 + row)*NH + h)*64 + ch*8);
    }
    CP_COMMIT();
    load_kv(0); CP_COMMIT();
    load_kv(1); CP_COMMIT();

    CP_WAIT2();          // Q ready
    __syncthreads();
    unsigned qf[4][4];
    #pragma unroll
    for (int ks = 0; ks < 4; ks++) {
        int row = 16*w + (part & 1)*8 + l7;
        int ch  = ks*2 + (part >> 1);
        ldmx4(qf[ks], &Qs[swz(row, ch)]);
    }

    float o_acc[8][4] = {};
    float rs0 = 0.f, rs1 = 0.f;

    const int T = NLC/128;
    for (int kt = 0; kt < T; kt++) {
        if (kt + 1 < T) { CP_WAIT1(); } else { CP_WAIT0(); }
        __syncthreads();
        if (kt + 2 < T) { load_kv(kt + 2); CP_COMMIT(); }

        int st = kt % 3;
        const bf16* Ks = (const bf16*)(sm + 16384 + st*32768);
        const bf16* Vs = Ks + 8192;

        #pragma unroll
        for (int half = 0; half < 2; half++) {
            const int koff = half*64;
            float s[8][4] = {};
            #pragma unroll
            for (int ks = 0; ks < 4; ks++) {
                #pragma unroll
                for (int p = 0; p < 4; p++) {
                    int row = koff + p*16 + (part >> 1)*8 + l7;
                    int ch  = ks*2 + (part & 1);
                    unsigned r4[4];
                    ldmx4(r4, &Ks[swz(row, ch)]);
                    mma16(s[2*p],   qf[ks], r4);
                    mma16(s[2*p+1], qf[ks], r4 + 2);
                }
            }
            #pragma unroll
            for (int nt = 0; nt < 8; nt++) {
                s[nt][0] = __expf(s[nt][0] - 10.0f);
                s[nt][1] = __expf(s[nt][1] - 10.0f);
                s[nt][2] = __expf(s[nt][2] - 10.0f);
                s[nt][3] = __expf(s[nt][3] - 10.0f);
                rs0 += s[nt][0] + s[nt][1];
                rs1 += s[nt][2] + s[nt][3];
            }
            #pragma unroll
            for (int ks = 0; ks < 4; ks++) {
                unsigned ap[4];
                ap[0] = packbf(s[2*ks][0],   s[2*ks][1]);
                ap[1] = packbf(s[2*ks][2],   s[2*ks][3]);
                ap[2] = packbf(s[2*ks+1][0], s[2*ks+1][1]);
                ap[3] = packbf(s[2*ks+1][2], s[2*ks+1][3]);
                #pragma unroll
                for (int p = 0; p < 4; p++) {
                    int row = koff + ks*16 + (part & 1)*8 + l7;
                    int ch  = p*2 + (part >> 1);
                    unsigned r4[4];
                    ldmx4t(r4, &Vs[swz(row, ch)]);
                    mma16(o_acc[2*p],   ap, r4);
                    mma16(o_acc[2*p+1], ap, r4 + 2);
                }
            }
        }
    }

    #pragma unroll
    for (int off = 1; off <= 2; off <<= 1) {
        rs0 += __shfl_xor_sync(0xffffffffu, rs0, off);
        rs1 += __shfl_xor_sync(0xffffffffu, rs1, off);
    }
    float inv0 = 1.f / rs0, inv1 = 1.f / rs1;
    size_t r0 = m0 + 16*w + g, r1 = r0 + 8;
    #pragma unroll
    for (int nt = 0; nt < 8; nt++) {
        size_t cc = nt*8 + 2*t4;
        *(unsigned*)&O[((size_t)(b*NL + r0)*NH + h)*64 + cc] =
            packbf(o_acc[nt][0]*inv0, o_acc[nt][1]*inv0);
        *(unsigned*)&O[((size_t)(b*NL + r1)*NH + h)*64 + cc] =
            packbf(o_acc[nt][2]*inv1, o_acc[nt][3]*inv1);
    }
}

// ---------------- launcher: fork-join multi-stream pipeline ----------------
static cudaStream_t g_s1 = nullptr, g_s2 = nullptr;
static cudaEvent_t  g_eFork = nullptr, g_eQ = nullptr, g_eWout = nullptr,
                    g_eWkv = nullptr, g_eXcb = nullptr, g_eV = nullptr;

extern "C" void kernel_launch(void* const* d_in, const int* in_sizes, int n_in,
                              void* d_out, int out_size) {
    const float* x      = (const float*)d_in[0];
    const float* pos    = (const float*)d_in[1];
    const float* x_cross= (const float*)d_in[2];
    const float* posc   = (const float*)d_in[3];
    const float* nscale = (const float*)d_in[4];
    const float* ncscale= (const float*)d_in[5];
    const float* q_w    = (const float*)d_in[6];
    const float* kv_w   = (const float*)d_in[7];
    const float* hscale = (const float*)d_in[8];
    const float* out_w  = (const float*)d_in[9];
    float* out = (float*)d_out;

    if (!g_s1) {
        cudaStreamCreateWithFlags(&g_s1, cudaStreamNonBlocking);
        cudaStreamCreateWithFlags(&g_s2, cudaStreamNonBlocking);
        cudaEventCreateWithFlags(&g_eFork, cudaEventDisableTiming);
        cudaEventCreateWithFlags(&g_eQ,    cudaEventDisableTiming);
        cudaEventCreateWithFlags(&g_eWout, cudaEventDisableTiming);
        cudaEventCreateWithFlags(&g_eWkv,  cudaEventDisableTiming);
        cudaEventCreateWithFlags(&g_eXcb,  cudaEventDisableTiming);
        cudaEventCreateWithFlags(&g_eV,    cudaEventDisableTiming);
    }

    bf16 *xnb, *xcb, *wq, *wkv, *wout, *qpre, *kvb, *qb, *kb, *ob;
    cudaGetSymbolAddress((void**)&xnb, g_xnb);
    cudaGetSymbolAddress((void**)&xcb, g_xcb);
    cudaGetSymbolAddress((void**)&wq,  g_wq);
    cudaGetSymbolAddress((void**)&wkv, g_wkv);
    cudaGetSymbolAddress((void**)&wout,g_wout);
    cudaGetSymbolAddress((void**)&qpre,g_qpre);
    cudaGetSymbolAddress((void**)&kvb, g_kvb);
    cudaGetSymbolAddress((void**)&qb,  g_qb);
    cudaGetSymbolAddress((void**)&kb,  g_kb);
    cudaGetSymbolAddress((void**)&ob,  g_ob);

    cudaFuncSetAttribute(gemm_bf<bf16,false>, cudaFuncAttributeMaxDynamicSharedMemorySize, GEMM_SMEM);
    cudaFuncSetAttribute(gemm_bf<float,true>, cudaFuncAttributeMaxDynamicSharedMemorySize, GEMM_SMEM);
    cudaFuncSetAttribute(attn_bf16, cudaFuncAttributeMaxDynamicSharedMemorySize, ATT_SMEM);

    // fork side streams off the capture-origin (legacy) stream
    cudaEventRecord(g_eFork, 0);
    cudaStreamWaitEvent(g_s1, g_eFork, 0);
    cudaStreamWaitEvent(g_s2, g_eFork, 0);

    // ---- s1: q-side chain (independent until attention) ----
    f2b_k<<<(DMODEL*DMODEL/4 + 255)/256, 256, 0, g_s1>>>(q_w, wq, DMODEL*DMODEL/4);
    rmsnorm_k<<<NROWS/8, 256, 0, g_s1>>>(x, nscale, xnb);
    gemm_bf<bf16,false><<<dim3(8, NROWS/128), 256, GEMM_SMEM, g_s1>>>(
        xnb, wq, nullptr, qpre, NROWS, DMODEL, DMODEL);
    qkprep_k<<<NROWS*NH/16, 256, 0, g_s1>>>(qpre, DMODEL, pos, hscale, qb);
    cudaEventRecord(g_eQ, g_s1);

    // ---- s2: weight converts + V-half projection ----
    f2b_k<<<(2*DMODEL*DMODEL/4 + 255)/256, 256, 0, g_s2>>>(kv_w, wkv, 2*DMODEL*DMODEL/4);
    cudaEventRecord(g_eWkv, g_s2);
    f2b_k<<<(DMODEL*DMODEL/4 + 255)/256, 256, 0, g_s2>>>(out_w, wout, DMODEL*DMODEL/4);
    cudaEventRecord(g_eWout, g_s2);

    // ---- s0 (critical path): rms_xc -> K-proj -> qkprep_k -> attn -> out-proj ----
    rmsnorm_k<<<NROWS/8, 256>>>(x_cross, ncscale, xcb);
    cudaEventRecord(g_eXcb, 0);

    // V-half projection on s2 (needs wkv + xcb), overlaps with K-half + qkprep_k on s0
    cudaStreamWaitEvent(g_s2, g_eXcb, 0);
    gemm_bf<bf16,false><<<dim3(8, NROWS/128), 256, GEMM_SMEM, g_s2>>>(
        xcb, wkv + DMODEL*DMODEL, nullptr, kvb + DMODEL, NROWS, DMODEL, 2*DMODEL);
    cudaEventRecord(g_eV, g_s2);

    // K-half projection on s0
    cudaStreamWaitEvent(0, g_eWkv, 0);
    gemm_bf<bf16,false><<<dim3(8, NROWS/128), 256, GEMM_SMEM>>>(
        xcb, wkv, nullptr, kvb, NROWS, DMODEL, 2*DMODEL);
    qkprep_k<<<NROWS*NH/16, 256>>>(kvb, 2*DMODEL, posc, hscale, kb);

    cudaStreamWaitEvent(0, g_eQ, 0);   // join q chain
    cudaStreamWaitEvent(0, g_eV, 0);   // join V-half
    attn_bf16<<<dim3(NL/128, NH, NB), 256, ATT_SMEM>>>(qb, kb, kvb, ob);

    cudaStreamWaitEvent(0, g_eWout, 0); // join wout convert
    gemm_bf<float,true><<<dim3(8, NROWS/128), 256, GEMM_SMEM>>>(
        ob, wout, x, out, NROWS, DMODEL, DMODEL);
}

// round 10
// speedup vs baseline: 9.5889x; 1.1036x over previous
#include <cuda_runtime.h>
#include <cuda_bf16.h>
#include <math.h>
#include <stdint.h>

#define NB 2
#define NL 2048
#define NLC 2048
#define NH 16
#define DMODEL 1024
#define NROWS (NB*NL)

typedef __nv_bfloat16 bf16;

// ---------------- scratch ----------------
__device__ bf16 g_xnb[NROWS*DMODEL];
__device__ bf16 g_xcb[NROWS*DMODEL];
__device__ bf16 g_wq [DMODEL*DMODEL];
__device__ bf16 g_wkv[2*DMODEL*DMODEL];
__device__ bf16 g_wout[DMODEL*DMODEL];
__device__ bf16 g_qpre[NROWS*DMODEL];
__device__ bf16 g_kvb [NROWS*2*DMODEL];
__device__ bf16 g_qb[NROWS*DMODEL];
__device__ bf16 g_kb[NROWS*DMODEL];
__device__ bf16 g_ob[NROWS*DMODEL];
__device__ float g_ftab[160];

// ---------------- PTX helpers ----------------
__device__ __forceinline__ uint32_t s2u(const void* p) {
    return (uint32_t)__cvta_generic_to_shared(p);
}
__device__ __forceinline__ void cp16(void* s, const void* g) {
    asm volatile("cp.async.cg.shared.global [%0], [%1], 16;\n" :: "r"(s2u(s)), "l"(g));
}
#define CP_COMMIT() asm volatile("cp.async.commit_group;\n")
#define CP_WAIT0()  asm volatile("cp.async.wait_group 0;\n")
#define CP_WAIT1()  asm volatile("cp.async.wait_group 1;\n")
#define CP_WAIT2()  asm volatile("cp.async.wait_group 2;\n")

__device__ __forceinline__ void ldmx4(unsigned* r, const void* p) {
    asm volatile("ldmatrix.sync.aligned.m8n8.x4.shared.b16 {%0,%1,%2,%3}, [%4];"
                 : "=r"(r[0]), "=r"(r[1]), "=r"(r[2]), "=r"(r[3]) : "r"(s2u(p)));
}
__device__ __forceinline__ void ldmx4t(unsigned* r, const void* p) {
    asm volatile("ldmatrix.sync.aligned.m8n8.x4.trans.shared.b16 {%0,%1,%2,%3}, [%4];"
                 : "=r"(r[0]), "=r"(r[1]), "=r"(r[2]), "=r"(r[3]) : "r"(s2u(p)));
}
__device__ __forceinline__ void mma16(float* d, const unsigned* a, const unsigned* b) {
    asm("mma.sync.aligned.m16n8k16.row.col.f32.bf16.bf16.f32 "
        "{%0,%1,%2,%3},{%4,%5,%6,%7},{%8,%9},{%0,%1,%2,%3};"
        : "+f"(d[0]), "+f"(d[1]), "+f"(d[2]), "+f"(d[3])
        : "r"(a[0]), "r"(a[1]), "r"(a[2]), "r"(a[3]), "r"(b[0]), "r"(b[1]));
}
__device__ __forceinline__ int swz(int row, int ch) {   // elem idx, 64-elem (128B) rows
    return row*64 + ((ch ^ (row & 7)) << 3);
}
__device__ __forceinline__ unsigned packbf(float a, float b) {
    __nv_bfloat162 h = __floats2bfloat162_rn(a, b);
    return *(unsigned*)&h;
}

// ---------------- RoPE freq table: fr[i] = pi * 10^(i/160) ----------------
__global__ void ftab_k() {
    int i = threadIdx.x;
    if (i < 160) g_ftab[i] = 3.14159265358979323846f * exp10f((float)i * (1.0f/160.0f));
}

// ---------------- fp32 -> bf16 convert ----------------
__global__ __launch_bounds__(256) void f2b_k(const float* __restrict__ src,
                                             bf16* __restrict__ dst, int n4) {
    int i = blockIdx.x*256 + threadIdx.x;
    if (i >= n4) return;
    float4 v = ((const float4*)src)[i];
    ((__nv_bfloat162*)dst)[2*i]   = __floats2bfloat162_rn(v.x, v.y);
    ((__nv_bfloat162*)dst)[2*i+1] = __floats2bfloat162_rn(v.z, v.w);
}

// ---------------- RMS norm: warp per row, MLP=8 ----------------
__global__ __launch_bounds__(256) void rmsnorm_k(const float* __restrict__ x,
                                                 const float* __restrict__ scale,
                                                 bf16* __restrict__ out) {
    const int w = threadIdx.x >> 5, lane = threadIdx.x & 31;
    const size_t row = blockIdx.x*8 + w;
    const float4* xr = (const float4*)(x + row*DMODEL);
    const float4* sc = (const float4*)scale;
    float4 v[8];
    #pragma unroll
    for (int i = 0; i < 8; i++) v[i] = xr[lane + i*32];
    float ss = 0.f;
    #pragma unroll
    for (int i = 0; i < 8; i++)
        ss += v[i].x*v[i].x + v[i].y*v[i].y + v[i].z*v[i].z + v[i].w*v[i].w;
    #pragma unroll
    for (int o = 16; o; o >>= 1) ss += __shfl_xor_sync(0xffffffffu, ss, o);
    float inv = rsqrtf(ss * (1.0f/DMODEL) + 1e-6f);
    uint2* op = (uint2*)(out + row*DMODEL);
    #pragma unroll
    for (int i = 0; i < 8; i++) {
        float4 s = sc[lane + i*32];
        uint2 pk;
        pk.x = packbf(v[i].x*s.x*inv, v[i].y*s.y*inv);
        pk.y = packbf(v[i].z*s.z*inv, v[i].w*s.w*inv);
        op[lane + i*32] = pk;
    }
}

// ---------------- bf16 mma GEMM: C[M,cols] = A[M,K]@B[rows,K]^T (+skip) -----------
// 128x128 block, BK=64, 2-stage cp.async, 8 warps, 2 CTAs/SM.
#define GEMM_SMEM (2*32768)

template<typename OutT, bool ADD>
__global__ __launch_bounds__(256, 2) void gemm_bf(const bf16* __restrict__ A,
                                                  const bf16* __restrict__ B,
                                                  const float* __restrict__ skip,
                                                  OutT* __restrict__ C,
                                                  int M, int K, int ldc) {
    extern __shared__ char sm[];
    const int bm = blockIdx.y*128, bn = blockIdx.x*128;
    const int tid = threadIdx.x, w = tid >> 5, lane = tid & 31;
    const int g = lane >> 2, t4 = lane & 3;
    const int part = lane >> 3, l7 = lane & 7;
    const int wm = (w >> 2)*64, wn = (w & 3)*32;

    float acc[4][4][4] = {};
    const int T = K >> 6;

    auto load_tile = [&](int kt) {
        int st = kt & 1;
        char* As = sm + st*32768;
        char* Bs = As + 16384;
        int k0 = kt << 6;
        #pragma unroll
        for (int i = 0; i < 4; i++) {
            int c = tid + i*256, r = c >> 3, ch = c & 7;
            cp16(As + r*128 + ((ch ^ (r & 7)) << 4), A + (size_t)(bm + r)*K + k0 + ch*8);
            cp16(Bs + r*128 + ((ch ^ (r & 7)) << 4), B + (size_t)(bn + r)*K + k0 + ch*8);
        }
    };

    load_tile(0); CP_COMMIT();

    for (int kt = 0; kt < T; kt++) {
        CP_WAIT0();
        __syncthreads();   // all warps done with the other buffer; tile kt resident
        if (kt + 1 < T) { load_tile(kt + 1); CP_COMMIT(); }

        int st = kt & 1;
        const bf16* As = (const bf16*)(sm + st*32768);
        const bf16* Bs = (const bf16*)(sm + st*32768 + 16384);
        #pragma unroll
        for (int ks = 0; ks < 4; ks++) {
            unsigned af[4][4], bfr[4][2];
            #pragma unroll
            for (int mt = 0; mt < 4; mt++) {
                int row = wm + mt*16 + (part & 1)*8 + l7;
                int ch  = ks*2 + (part >> 1);
                ldmx4(af[mt], &As[swz(row, ch)]);
            }
            #pragma unroll
            for (int p = 0; p < 2; p++) {
                int row = wn + p*16 + (part >> 1)*8 + l7;
                int ch  = ks*2 + (part & 1);
                unsigned r4[4];
                ldmx4(r4, &Bs[swz(row, ch)]);
                bfr[2*p][0] = r4[0]; bfr[2*p][1] = r4[1];
                bfr[2*p+1][0] = r4[2]; bfr[2*p+1][1] = r4[3];
            }
            #pragma unroll
            for (int mt = 0; mt < 4; mt++)
                #pragma unroll
                for (int nt = 0; nt < 4; nt++)
                    mma16(acc[mt][nt], af[mt], bfr[nt]);
        }
        __syncthreads();   // compute done before next overwrite of this buffer
    }

    #pragma unroll
    for (int mt = 0; mt < 4; mt++) {
        size_t r0 = bm + wm + mt*16 + g, r1 = r0 + 8;
        #pragma unroll
        for (int nt = 0; nt < 4; nt++) {
            size_t cc = bn + wn + nt*8 + 2*t4;
            float2 v0 = make_float2(acc[mt][nt][0], acc[mt][nt][1]);
            float2 v1 = make_float2(acc[mt][nt][2], acc[mt][nt][3]);
            if (ADD) {
                float2 s0 = *(const float2*)&skip[r0*ldc + cc];
                float2 s1 = *(const float2*)&skip[r1*ldc + cc];
                v0.x += s0.x; v0.y += s0.y; v1.x += s1.x; v1.y += s1.y;
            }
            if (sizeof(OutT) == 4) {
                *(float2*)&((float*)C)[r0*ldc + cc] = v0;
                *(float2*)&((float*)C)[r1*ldc + cc] = v1;
            } else {
                *(unsigned*)&((bf16*)C)[r0*ldc + cc] = packbf(v0.x, v0.y);
                *(unsigned*)&((bf16*)C)[r1*ldc + cc] = packbf(v1.x, v1.y);
            }
        }
    }
}

// ---------------- cosine scale + 3-axis RoPE: warp-per-vector, freq table ---------
__global__ __launch_bounds__(256) void qkprep_k(const bf16* __restrict__ src, int sstride,
                                                const float* __restrict__ pos,
                                                const float* __restrict__ head_scale,
                                                bf16* __restrict__ dst) {
    const int warp = threadIdx.x >> 5, lane = threadIdx.x & 31;
    const int gv0 = (blockIdx.x*8 + warp)*2;
    const int srcl = (lane < 15) ? lane + 15 : lane - 15;

    #pragma unroll
    for (int vv = 0; vv < 2; vv++) {
        int gv = gv0 + vv;
        int row = gv >> 4, h = gv & 15;
        unsigned u = ((const unsigned*)(src + (size_t)row*sstride + h*64))[lane];
        __nv_bfloat162 bb = *(__nv_bfloat162*)&u;
        float f0 = __bfloat162float(bb.x), f1 = __bfloat162float(bb.y);
        float ss = f0*f0 + f1*f1;
        #pragma unroll
        for (int o = 16; o; o >>= 1) ss += __shfl_xor_sync(0xffffffffu, ss, o);
        float cs = sqrtf(head_scale[h]) * rsqrtf(ss + 1e-6f);
        float p0 = __shfl_sync(0xffffffffu, f0, srcl);
        float p1 = __shfl_sync(0xffffffffu, f1, srcl);
        float out0, out1;
        if (lane < 30) {
            int i0 = (lane < 15) ? 2*lane : 2*lane - 30;   // i in [0,30), even
            int a0 = i0/10, j0 = i0 - a0*10;
            int i1 = i0 + 1;
            int a1 = i1/10, j1 = i1 - a1*10;
            float fr0 = g_ftab[j0*16 + h];
            float fr1 = g_ftab[j1*16 + h];
            float th0 = pos[(size_t)row*3 + a0]*fr0;
            float th1 = pos[(size_t)row*3 + a1]*fr1;
            float s0, c0, s1, c1;
            __sincosf(th0, &s0, &c0);
            __sincosf(th1, &s1, &c1);
            if (lane < 15) { out0 = cs*(f0*c0 - p0*s0); out1 = cs*(f1*c1 - p1*s1); }
            else           { out0 = cs*(f0*c0 + p0*s0); out1 = cs*(f1*c1 + p1*s1); }
        } else {
            out0 = cs*f0; out1 = cs*f1;
        }
        ((unsigned*)(dst + (size_t)row*DMODEL + h*64))[lane] = packbf(out0, out1);
    }
}

// ---------------- flash attention: 2-stage, 2 CTAs/SM ----------------
#define ATT_SMEM (16384 + 2*32768)   // Qs + 2 x (K 16KB + V 16KB) = 80KB

__global__ __launch_bounds__(256, 2) void attn_bf16(const bf16* __restrict__ Q,
                                                    const bf16* __restrict__ Kb,
                                                    const bf16* __restrict__ KVb,
                                                    bf16* __restrict__ O) {
    extern __shared__ char sm[];
    bf16* Qs = (bf16*)sm;
    const int b = blockIdx.z, h = blockIdx.y, m0 = blockIdx.x*128;
    const int tid = threadIdx.x, w = tid >> 5, lane = tid & 31;
    const int g = lane >> 2, t4 = lane & 3;
    const int part = lane >> 3, l7 = lane & 7;

    auto load_kv = [&](int kt) {
        int st = kt & 1;
        bf16* Ks = (bf16*)(sm + 16384 + st*32768);
        bf16* Vs = Ks + 8192;
        int n0 = kt << 7;
        #pragma unroll
        for (int i = 0; i < 4; i++) {
            int c = tid + i*256, row = c >> 3, ch = c & 7;
            cp16(&Ks[swz(row, ch)],
                 Kb + ((size_t)(b*NLC + n0 + row)*NH + h)*64 + ch*8);
            cp16(&Vs[swz(row, ch)],
                 KVb + (size_t)(b*NLC + n0 + row)*(2*DMODEL) + DMODEL + h*64 + ch*8);
        }
    };

    #pragma unroll
    for (int i = 0; i < 4; i++) {
        int c = tid + i*256, row = c >> 3, ch = c & 7;
        cp16(&Qs[swz(row, ch)], Q + ((size_t)(b*NL + m0 + row)*NH + h)*64 + ch*8);
    }
    load_kv(0);
    CP_COMMIT();

    CP_WAIT0();          // Q + KV0 ready
    __syncthreads();
    unsigned qf[4][4];
    #pragma unroll
    for (int ks = 0; ks < 4; ks++) {
        int row = 16*w + (part & 1)*8 + l7;
        int ch  = ks*2 + (part >> 1);
        ldmx4(qf[ks], &Qs[swz(row, ch)]);
    }

    float o_acc[8][4] = {};
    float rs0 = 0.f, rs1 = 0.f;

    const int T = NLC/128;
    for (int kt = 0; kt < T; kt++) {
        if (kt > 0) {
            CP_WAIT0();
            __syncthreads();
        }
        if (kt + 1 < T) { load_kv(kt + 1); CP_COMMIT(); }

        int st = kt & 1;
        const bf16* Ks = (const bf16*)(sm + 16384 + st*32768);
        const bf16* Vs = Ks + 8192;

        #pragma unroll
        for (int half = 0; half < 2; half++) {
            const int koff = half*64;
            float s[8][4] = {};
            #pragma unroll
            for (int ks = 0; ks < 4; ks++) {
                #pragma unroll
                for (int p = 0; p < 4; p++) {
                    int row = koff + p*16 + (part >> 1)*8 + l7;
                    int ch  = ks*2 + (part & 1);
                    unsigned r4[4];
                    ldmx4(r4, &Ks[swz(row, ch)]);
                    mma16(s[2*p],   qf[ks], r4);
                    mma16(s[2*p+1], qf[ks], r4 + 2);
                }
            }
            #pragma unroll
            for (int nt = 0; nt < 8; nt++) {
                s[nt][0] = __expf(s[nt][0] - 10.0f);
                s[nt][1] = __expf(s[nt][1] - 10.0f);
                s[nt][2] = __expf(s[nt][2] - 10.0f);
                s[nt][3] = __expf(s[nt][3] - 10.0f);
                rs0 += s[nt][0] + s[nt][1];
                rs1 += s[nt][2] + s[nt][3];
            }
            #pragma unroll
            for (int ks = 0; ks < 4; ks++) {
                unsigned ap[4];
                ap[0] = packbf(s[2*ks][0],   s[2*ks][1]);
                ap[1] = packbf(s[2*ks][2],   s[2*ks][3]);
                ap[2] = packbf(s[2*ks+1][0], s[2*ks+1][1]);
                ap[3] = packbf(s[2*ks+1][2], s[2*ks+1][3]);
                #pragma unroll
                for (int p = 0; p < 4; p++) {
                    int row = koff + ks*16 + (part & 1)*8 + l7;
                    int ch  = p*2 + (part >> 1);
                    unsigned r4[4];
                    ldmx4t(r4, &Vs[swz(row, ch)]);
                    mma16(o_acc[2*p],   ap, r4);
                    mma16(o_acc[2*p+1], ap, r4 + 2);
                }
            }
        }
        __syncthreads();   // all warps done with stage st before it is overwritten
    }

    #pragma unroll
    for (int off = 1; off <= 2; off <<= 1) {
        rs0 += __shfl_xor_sync(0xffffffffu, rs0, off);
        rs1 += __shfl_xor_sync(0xffffffffu, rs1, off);
    }
    float inv0 = 1.f / rs0, inv1 = 1.f / rs1;
    size_t r0 = m0 + 16*w + g, r1 = r0 + 8;
    #pragma unroll
    for (int nt = 0; nt < 8; nt++) {
        size_t cc = nt*8 + 2*t4;
        *(unsigned*)&O[((size_t)(b*NL + r0)*NH + h)*64 + cc] =
            packbf(o_acc[nt][0]*inv0, o_acc[nt][1]*inv0);
        *(unsigned*)&O[((size_t)(b*NL + r1)*NH + h)*64 + cc] =
            packbf(o_acc[nt][2]*inv1, o_acc[nt][3]*inv1);
    }
}

// ---------------- launcher: fork-join multi-stream pipeline ----------------
static cudaStream_t g_s1 = nullptr, g_s2 = nullptr;
static cudaEvent_t  g_eFork = nullptr, g_eQ = nullptr, g_eWout = nullptr,
                    g_eWkv = nullptr, g_eXcb = nullptr, g_eV = nullptr;

extern "C" void kernel_launch(void* const* d_in, const int* in_sizes, int n_in,
                              void* d_out, int out_size) {
    const float* x      = (const float*)d_in[0];
    const float* pos    = (const float*)d_in[1];
    const float* x_cross= (const float*)d_in[2];
    const float* posc   = (const float*)d_in[3];
    const float* nscale = (const float*)d_in[4];
    const float* ncscale= (const float*)d_in[5];
    const float* q_w    = (const float*)d_in[6];
    const float* kv_w   = (const float*)d_in[7];
    const float* hscale = (const float*)d_in[8];
    const float* out_w  = (const float*)d_in[9];
    float* out = (float*)d_out;

    if (!g_s1) {
        cudaStreamCreateWithFlags(&g_s1, cudaStreamNonBlocking);
        cudaStreamCreateWithFlags(&g_s2, cudaStreamNonBlocking);
        cudaEventCreateWithFlags(&g_eFork, cudaEventDisableTiming);
        cudaEventCreateWithFlags(&g_eQ,    cudaEventDisableTiming);
        cudaEventCreateWithFlags(&g_eWout, cudaEventDisableTiming);
        cudaEventCreateWithFlags(&g_eWkv,  cudaEventDisableTiming);
        cudaEventCreateWithFlags(&g_eXcb,  cudaEventDisableTiming);
        cudaEventCreateWithFlags(&g_eV,    cudaEventDisableTiming);
    }

    bf16 *xnb, *xcb, *wq, *wkv, *wout, *qpre, *kvb, *qb, *kb, *ob;
    cudaGetSymbolAddress((void**)&xnb, g_xnb);
    cudaGetSymbolAddress((void**)&xcb, g_xcb);
    cudaGetSymbolAddress((void**)&wq,  g_wq);
    cudaGetSymbolAddress((void**)&wkv, g_wkv);
    cudaGetSymbolAddress((void**)&wout,g_wout);
    cudaGetSymbolAddress((void**)&qpre,g_qpre);
    cudaGetSymbolAddress((void**)&kvb, g_kvb);
    cudaGetSymbolAddress((void**)&qb,  g_qb);
    cudaGetSymbolAddress((void**)&kb,  g_kb);
    cudaGetSymbolAddress((void**)&ob,  g_ob);

    cudaFuncSetAttribute(gemm_bf<bf16,false>, cudaFuncAttributeMaxDynamicSharedMemorySize, GEMM_SMEM);
    cudaFuncSetAttribute(gemm_bf<float,true>, cudaFuncAttributeMaxDynamicSharedMemorySize, GEMM_SMEM);
    cudaFuncSetAttribute(attn_bf16, cudaFuncAttributeMaxDynamicSharedMemorySize, ATT_SMEM);

    // fork side streams off the capture-origin (legacy) stream
    cudaEventRecord(g_eFork, 0);
    cudaStreamWaitEvent(g_s1, g_eFork, 0);
    cudaStreamWaitEvent(g_s2, g_eFork, 0);

    // ---- s1: q-side chain (independent until attention) ----
    f2b_k<<<(DMODEL*DMODEL/4 + 255)/256, 256, 0, g_s1>>>(q_w, wq, DMODEL*DMODEL/4);
    rmsnorm_k<<<NROWS/8, 256, 0, g_s1>>>(x, nscale, xnb);
    gemm_bf<bf16,false><<<dim3(8, NROWS/128), 256, GEMM_SMEM, g_s1>>>(
        xnb, wq, nullptr, qpre, NROWS, DMODEL, DMODEL);
    qkprep_k<<<NROWS*NH/16, 256, 0, g_s1>>>(qpre, DMODEL, pos, hscale, qb);
    cudaEventRecord(g_eQ, g_s1);

    // ---- s2: freq table + weight converts + V-half projection ----
    ftab_k<<<1, 160, 0, g_s2>>>();
    f2b_k<<<(2*DMODEL*DMODEL/4 + 255)/256, 256, 0, g_s2>>>(kv_w, wkv, 2*DMODEL*DMODEL/4);
    cudaEventRecord(g_eWkv, g_s2);
    f2b_k<<<(DMODEL*DMODEL/4 + 255)/256, 256, 0, g_s2>>>(out_w, wout, DMODEL*DMODEL/4);
    cudaEventRecord(g_eWout, g_s2);

    // ---- s0 (critical path): rms_xc -> K-proj -> qkprep_k -> attn -> out-proj ----
    rmsnorm_k<<<NROWS/8, 256>>>(x_cross, ncscale, xcb);
    cudaEventRecord(g_eXcb, 0);

    // V-half projection on s2 (needs wkv + xcb), overlaps with K-half + qkprep_k on s0
    cudaStreamWaitEvent(g_s2, g_eXcb, 0);
    gemm_bf<bf16,false><<<dim3(8, NROWS/128), 256, GEMM_SMEM, g_s2>>>(
        xcb, wkv + DMODEL*DMODEL, nullptr, kvb + DMODEL, NROWS, DMODEL, 2*DMODEL);
    cudaEventRecord(g_eV, g_s2);

    // K-half projection on s0
    cudaStreamWaitEvent(0, g_eWkv, 0);
    gemm_bf<bf16,false><<<dim3(8, NROWS/128), 256, GEMM_SMEM>>>(
        xcb, wkv, nullptr, kvb, NROWS, DMODEL, 2*DMODEL);
    qkprep_k<<<NROWS*NH/16, 256>>>(kvb, 2*DMODEL, posc, hscale, kb);

    cudaStreamWaitEvent(0, g_eQ, 0);   // join q chain
    cudaStreamWaitEvent(0, g_eV, 0);   // join V-half
    attn_bf16<<<dim3(NL/128, NH, NB), 256, ATT_SMEM>>>(qb, kb, kvb, ob);

    cudaStreamWaitEvent(0, g_eWout, 0); // join wout convert
    gemm_bf<float,true><<<dim3(8, NROWS/128), 256, GEMM_SMEM>>>(
        ob, wout, x, out, NROWS, DMODEL, DMODEL);
}